// round 7
// baseline (speedup 1.0000x reference)
#include <cuda_runtime.h>
#include <cuda_bf16.h>
#include <mma.h>
#include <cstdint>

using namespace nvcuda;

#define NEGC -1000000000.0f
#define B_ 8
#define S_ 4096
#define D_ 256
#define KC 64
#define NSPLIT 8

// ---------------------------------------------------------------------------
// Scratch (__device__ globals; no allocation allowed)
// ---------------------------------------------------------------------------
__device__ __nv_bfloat16 g_Kc[B_ * S_ * D_];              // [b][s][d]  K * invb
__device__ __nv_bfloat16 g_Vc[B_ * S_ * D_];              // [b][s][e]  V
__device__ __nv_bfloat16 g_Qc[B_ * S_ * D_];              // [b][s][d]  Q/sumsq (masked=0)
__device__ float         g_s1part[NSPLIT * B_ * D_ * D_]; // per-split partials
__device__ __nv_bfloat16 g_s1c[B_ * D_ * D_];             // [b][d][e]  bf16
__device__ float         g_t[B_ * D_];                    // exact colsum (masked rows)
__device__ unsigned char g_msk[B_ * S_];
__device__ int           g_mask_mode;                     // 0=bool,1=int32,2=float32

// ---------------------------------------------------------------------------
// Helpers
// ---------------------------------------------------------------------------
__device__ __forceinline__ void cp16(void* smem_dst, const void* gsrc) {
    uint32_t a = (uint32_t)__cvta_generic_to_shared(smem_dst);
    asm volatile("cp.async.cg.shared.global [%0], [%1], 16;" :: "r"(a), "l"(gsrc));
}
__device__ __forceinline__ void cp_commit() { asm volatile("cp.async.commit_group;"); }
#define CP_WAIT(N) asm volatile("cp.async.wait_group %0;" :: "n"(N))

__device__ __forceinline__ uint4 pack8(float4 a, float4 b, float m) {
    __nv_bfloat162 h0 = __floats2bfloat162_rn(a.x * m, a.y * m);
    __nv_bfloat162 h1 = __floats2bfloat162_rn(a.z * m, a.w * m);
    __nv_bfloat162 h2 = __floats2bfloat162_rn(b.x * m, b.y * m);
    __nv_bfloat162 h3 = __floats2bfloat162_rn(b.z * m, b.w * m);
    uint4 o;
    o.x = *reinterpret_cast<uint32_t*>(&h0);
    o.y = *reinterpret_cast<uint32_t*>(&h1);
    o.z = *reinterpret_cast<uint32_t*>(&h2);
    o.w = *reinterpret_cast<uint32_t*>(&h3);
    return o;
}

// ---------------------------------------------------------------------------
// Block 0: zero g_t.  Block 1: mask dtype detect.
// ---------------------------------------------------------------------------
__global__ void zero_detect_kernel(const unsigned int* __restrict__ m) {
    if (blockIdx.x == 0) {
        reinterpret_cast<float4*>(g_t)[threadIdx.x] = make_float4(0.f, 0.f, 0.f, 0.f);
        reinterpret_cast<float4*>(g_t)[threadIdx.x + 256] = make_float4(0.f, 0.f, 0.f, 0.f);
    } else {
        __shared__ int s_big, s_odd;
        if (threadIdx.x == 0) { s_big = 0; s_odd = 0; }
        __syncthreads();
        int big = 0, odd = 0;
        for (int i = threadIdx.x; i < (B_ * S_) / 4; i += blockDim.x) {
            unsigned int w = m[i];
            unsigned int b0 = w & 0xFFu, b1 = (w >> 8) & 0xFFu,
                         b2 = (w >> 16) & 0xFFu, b3 = w >> 24;
            if (b0 > 1u || b1 > 1u || b2 > 1u || b3 > 1u) big = 1;
            if (w != 0u && w != 1u) odd = 1;
        }
        if (big) s_big = 1;
        if (odd) s_odd = 1;
        __syncthreads();
        if (threadIdx.x == 0) g_mask_mode = s_big ? 2 : (s_odd ? 0 : 1);
    }
}

// ---------------------------------------------------------------------------
// Fused prep.  z==0: KV pass (invb, Kc, Vc, exact t accumulation).
//              z==1: Q pass (sumsq, Qc, mask byte).
// grid (S/32, B, 2), 256 threads.
// ---------------------------------------------------------------------------
__global__ __launch_bounds__(256) void prep_kernel(const float* __restrict__ Q,
                                                   const float* __restrict__ K,
                                                   const float* __restrict__ V,
                                                   const void* __restrict__ m) {
    __shared__ float Vsm[32][264];
    __shared__ float csm[32];
    const int b = blockIdx.y, s0 = blockIdx.x * 32;
    const int tid = threadIdx.x, wid = tid >> 5, lane = tid & 31;
    const size_t base = ((size_t)b * S_ + s0) * D_;

    if (blockIdx.z == 0) {
#pragma unroll
        for (int i = 0; i < 4; i++) {
            int r = wid * 4 + i;
            const float4* kr = reinterpret_cast<const float4*>(K + base + (size_t)r * D_) + lane * 2;
            float4 k0 = kr[0], k1 = kr[1];
            float sk = k0.x * k0.x + k0.y * k0.y + k0.z * k0.z + k0.w * k0.w
                     + k1.x * k1.x + k1.y * k1.y + k1.z * k1.z + k1.w * k1.w;
            float rk = k0.x + k0.y + k0.z + k0.w + k1.x + k1.y + k1.z + k1.w;
#pragma unroll
            for (int o = 16; o; o >>= 1) {
                sk += __shfl_xor_sync(0xFFFFFFFFu, sk, o);
                rk += __shfl_xor_sync(0xFFFFFFFFu, rk, o);
            }
            float ib = 1.0f / sk;
            reinterpret_cast<uint4*>(g_Kc)[(base + (size_t)r * D_) / 8 + lane] = pack8(k0, k1, ib);

            const float4* vr = reinterpret_cast<const float4*>(V + base + (size_t)r * D_) + lane * 2;
            float4 v0 = vr[0], v1 = vr[1];
            *reinterpret_cast<float4*>(&Vsm[r][lane * 8])     = v0;
            *reinterpret_cast<float4*>(&Vsm[r][lane * 8 + 4]) = v1;
            reinterpret_cast<uint4*>(g_Vc)[(base + (size_t)r * D_) / 8 + lane] = pack8(v0, v1, 1.0f);
            if (lane == 0) csm[r] = rk * ib;
        }
        __syncthreads();
        float acc = 0.f;
        int e = tid;
#pragma unroll 8
        for (int s = 0; s < 32; s++) acc += csm[s] * Vsm[s][e];
        atomicAdd(&g_t[b * D_ + e], acc);
    } else {
        const int mode = g_mask_mode;
#pragma unroll
        for (int i = 0; i < 4; i++) {
            int r = wid * 4 + i;
            int g = b * S_ + s0 + r;
            const float4* qr = reinterpret_cast<const float4*>(Q + base + (size_t)r * D_) + lane * 2;
            float4 q0 = qr[0], q1 = qr[1];
            float sq = q0.x * q0.x + q0.y * q0.y + q0.z * q0.z + q0.w * q0.w
                     + q1.x * q1.x + q1.y * q1.y + q1.z * q1.z + q1.w * q1.w;
#pragma unroll
            for (int o = 16; o; o >>= 1) sq += __shfl_xor_sync(0xFFFFFFFFu, sq, o);
            bool mk;
            if (mode == 2)      mk = (reinterpret_cast<const float*>(m)[g] != 0.0f);
            else if (mode == 1) mk = (reinterpret_cast<const int*>(m)[g] != 0);
            else                mk = (reinterpret_cast<const unsigned char*>(m)[g] != 0);
            float mul = mk ? 0.0f : 1.0f / sq;
            reinterpret_cast<uint4*>(g_Qc)[(base + (size_t)r * D_) / 8 + lane] = pack8(q0, q1, mul);
            if (lane == 0) g_msk[g] = mk ? 1 : 0;
        }
    }
}

// ---------------------------------------------------------------------------
// GEMM1: s1part[split][b,d,e] = sum_{s in split} Kc[b,s,d] * Vc[b,s,e]
// A col-major [s][d], B row-major [s][e]. 128x128 CTA tile, 8 warps (4x2).
// 3-stage cp.async pipeline.  Epilogue stage buffer ALIASED in dynamic smem.
// grid (4 tiles, NSPLIT, B).  2 CTAs/SM.
// ---------------------------------------------------------------------------
#define AB1 8704               // 64*136 bf16 per operand per stage
#define G1_STAGE (2 * AB1)     // elems per stage (A then B)
#define G1_SMEM  (3 * G1_STAGE * (int)sizeof(__nv_bfloat16))   // 104448 B

__global__ __launch_bounds__(256, 2) void gemm1_kernel() {
    extern __shared__ __nv_bfloat16 dsm[];

    const int tid = threadIdx.x, wid = tid >> 5, lane = tid & 31;
    const int b = blockIdx.z;
    const int dt = (blockIdx.x >> 1) * 128, et = (blockIdx.x & 1) * 128;
    const int s0 = blockIdx.y * (S_ / NSPLIT);
    const int m0 = (wid >> 1) * 32, n0 = (wid & 1) * 64;
    const __nv_bfloat16* Kb = g_Kc + (size_t)b * S_ * D_;
    const __nv_bfloat16* Vb = g_Vc + (size_t)b * S_ * D_;

    wmma::fragment<wmma::accumulator, 16, 16, 16, float> acc[2][4];
#pragma unroll
    for (int i = 0; i < 2; i++)
#pragma unroll
        for (int j = 0; j < 4; j++) wmma::fill_fragment(acc[i][j], 0.0f);

    auto load = [&](int ch, int st) {
        const int ss = s0 + ch * KC;
        __nv_bfloat16* Ab = dsm + st * G1_STAGE;
        __nv_bfloat16* Bb = Ab + AB1;
#pragma unroll
        for (int it = 0; it < 4; it++) {
            int ci = tid + it * 256;
            int row = ci >> 4, c16 = ci & 15;
            cp16(Ab + row * 136 + c16 * 8, Kb + (size_t)(ss + row) * D_ + dt + c16 * 8);
            cp16(Bb + row * 136 + c16 * 8, Vb + (size_t)(ss + row) * D_ + et + c16 * 8);
        }
    };

    const int NCH = (S_ / NSPLIT) / KC;   // 8
    load(0, 0); cp_commit();
    load(1, 1); cp_commit();
    for (int ch = 0; ch < NCH; ch++) {
        if (ch + 2 < NCH)      { load(ch + 2, (ch + 2) % 3); cp_commit(); CP_WAIT(2); }
        else if (ch + 1 < NCH) { CP_WAIT(1); }
        else                   { CP_WAIT(0); }
        __syncthreads();
        __nv_bfloat16* Ab = dsm + (ch % 3) * G1_STAGE;
        __nv_bfloat16* Bb = Ab + AB1;
#pragma unroll
        for (int kk = 0; kk < KC / 16; kk++) {
            wmma::fragment<wmma::matrix_a, 16, 16, 16, __nv_bfloat16, wmma::col_major> fa[2];
            wmma::fragment<wmma::matrix_b, 16, 16, 16, __nv_bfloat16, wmma::row_major> fb[4];
#pragma unroll
            for (int i = 0; i < 2; i++)
                wmma::load_matrix_sync(fa[i], Ab + kk * 16 * 136 + m0 + 16 * i, 136);
#pragma unroll
            for (int j = 0; j < 4; j++)
                wmma::load_matrix_sync(fb[j], Bb + kk * 16 * 136 + n0 + 16 * j, 136);
#pragma unroll
            for (int i = 0; i < 2; i++)
#pragma unroll
                for (int j = 0; j < 4; j++)
                    wmma::mma_sync(acc[i][j], fa[i], fb[j], acc[i][j]);
        }
        __syncthreads();
    }

    // Epilogue: per-warp stage buffer aliased over (now dead) pipeline smem.
    float* stage = reinterpret_cast<float*>(dsm) + wid * 16 * 20;
    float* s1p = g_s1part + ((size_t)blockIdx.y * B_ + b) * D_ * D_;
    int r0 = lane >> 1, c0 = (lane & 1) * 8;
#pragma unroll
    for (int i = 0; i < 2; i++)
#pragma unroll
        for (int j = 0; j < 4; j++) {
            wmma::store_matrix_sync(stage, acc[i][j], 20, wmma::mem_row_major);
            __syncwarp();
            int gd = dt + m0 + 16 * i + r0;
            int ge = et + n0 + 16 * j + c0;
            float4 v0 = *reinterpret_cast<float4*>(&stage[r0 * 20 + c0]);
            float4 v1 = *reinterpret_cast<float4*>(&stage[r0 * 20 + c0 + 4]);
            *reinterpret_cast<float4*>(&s1p[(size_t)gd * D_ + ge])     = v0;
            *reinterpret_cast<float4*>(&s1p[(size_t)gd * D_ + ge + 4]) = v1;
            __syncwarp();
        }
}

// Reduce NSPLIT partials + convert to bf16.
__global__ void s1conv_kernel() {
    int i = blockIdx.x * 256 + threadIdx.x;   // B*D*D/4
    const int stride = (B_ * D_ * D_) / 4;
    float4 a = reinterpret_cast<const float4*>(g_s1part)[i];
#pragma unroll
    for (int sp = 1; sp < NSPLIT; sp++) {
        float4 p = reinterpret_cast<const float4*>(g_s1part)[sp * stride + i];
        a.x += p.x; a.y += p.y; a.z += p.z; a.w += p.w;
    }
    __nv_bfloat162 h0 = __floats2bfloat162_rn(a.x, a.y);
    __nv_bfloat162 h1 = __floats2bfloat162_rn(a.z, a.w);
    uint2 o;
    o.x = *reinterpret_cast<uint32_t*>(&h0);
    o.y = *reinterpret_cast<uint32_t*>(&h1);
    reinterpret_cast<uint2*>(g_s1c)[i] = o;
}

// ---------------------------------------------------------------------------
// GEMM2: out[b,s,e] = (1/256)*sum_d Qc[b,s,d]*s1c[b,d,e];
// masked rows -> NEG/256 * t[b,e] (exact fp32). 3-stage pipeline.
// grid (2 et, 32 st, B).  2 CTAs/SM.
// ---------------------------------------------------------------------------
#define A2BUF 9216             // 128*72
#define B2BUF 8704             // 64*136
#define G2_STAGE (A2BUF + B2BUF)
#define G2_SMEM  (3 * G2_STAGE * (int)sizeof(__nv_bfloat16))   // 107520 B

__global__ __launch_bounds__(256, 2) void gemm2_kernel(float* __restrict__ out) {
    extern __shared__ __nv_bfloat16 dsm[];

    const int tid = threadIdx.x, wid = tid >> 5, lane = tid & 31;
    const int b = blockIdx.z;
    const int et = blockIdx.x * 128, st = blockIdx.y * 128;
    const int m0 = (wid >> 1) * 32, n0 = (wid & 1) * 64;
    const __nv_bfloat16* Qb = g_Qc + ((size_t)b * S_ + st) * D_;
    const __nv_bfloat16* Sb = g_s1c + (size_t)b * D_ * D_;

    wmma::fragment<wmma::accumulator, 16, 16, 16, float> acc[2][4];
#pragma unroll
    for (int i = 0; i < 2; i++)
#pragma unroll
        for (int j = 0; j < 4; j++) wmma::fill_fragment(acc[i][j], 0.0f);

    auto load = [&](int ch, int st_) {
        __nv_bfloat16* Ab = dsm + st_ * G2_STAGE;
        __nv_bfloat16* Bb = Ab + A2BUF;
#pragma unroll
        for (int it = 0; it < 4; it++) {
            int ci = tid + it * 256;
            int arow = ci >> 3, ac8 = ci & 7;
            cp16(Ab + arow * 72 + ac8 * 8, Qb + (size_t)arow * D_ + ch * KC + ac8 * 8);
            int brow = ci >> 4, bc16 = ci & 15;
            cp16(Bb + brow * 136 + bc16 * 8, Sb + (size_t)(ch * KC + brow) * D_ + et + bc16 * 8);
        }
    };

    const int NCH = D_ / KC;   // 4
    load(0, 0); cp_commit();
    load(1, 1); cp_commit();
    for (int ch = 0; ch < NCH; ch++) {
        if (ch + 2 < NCH)      { load(ch + 2, (ch + 2) % 3); cp_commit(); CP_WAIT(2); }
        else if (ch + 1 < NCH) { CP_WAIT(1); }
        else                   { CP_WAIT(0); }
        __syncthreads();
        __nv_bfloat16* Ab = dsm + (ch % 3) * G2_STAGE;
        __nv_bfloat16* Bb = Ab + A2BUF;
#pragma unroll
        for (int kk = 0; kk < KC / 16; kk++) {
            wmma::fragment<wmma::matrix_a, 16, 16, 16, __nv_bfloat16, wmma::row_major> fa[2];
            wmma::fragment<wmma::matrix_b, 16, 16, 16, __nv_bfloat16, wmma::row_major> fb[4];
#pragma unroll
            for (int i = 0; i < 2; i++)
                wmma::load_matrix_sync(fa[i], Ab + (size_t)(m0 + 16 * i) * 72 + kk * 16, 72);
#pragma unroll
            for (int j = 0; j < 4; j++)
                wmma::load_matrix_sync(fb[j], Bb + kk * 16 * 136 + n0 + 16 * j, 136);
#pragma unroll
            for (int i = 0; i < 2; i++)
#pragma unroll
                for (int j = 0; j < 4; j++)
                    wmma::mma_sync(acc[i][j], fa[i], fb[j], acc[i][j]);
        }
        __syncthreads();
    }

    const float inv_d = 1.0f / 256.0f;
    const float mc = NEGC * inv_d;
    float* stage = reinterpret_cast<float*>(dsm) + wid * 16 * 20;
    float* ob = out + (size_t)b * S_ * D_;
    const float* tb = g_t + b * D_;
    int r0 = lane >> 1, c0 = (lane & 1) * 8;
#pragma unroll
    for (int i = 0; i < 2; i++) {
        int gs = st + m0 + 16 * i + r0;
        bool masked = (g_msk[b * S_ + gs] != 0);
#pragma unroll
        for (int j = 0; j < 4; j++) {
            wmma::store_matrix_sync(stage, acc[i][j], 20, wmma::mem_row_major);
            __syncwarp();
            int ge = et + n0 + 16 * j + c0;
            float4 v0, v1;
            if (masked) {
                v0 = make_float4(mc * tb[ge + 0], mc * tb[ge + 1], mc * tb[ge + 2], mc * tb[ge + 3]);
                v1 = make_float4(mc * tb[ge + 4], mc * tb[ge + 5], mc * tb[ge + 6], mc * tb[ge + 7]);
            } else {
                v0 = make_float4(stage[r0 * 20 + c0 + 0] * inv_d, stage[r0 * 20 + c0 + 1] * inv_d,
                                 stage[r0 * 20 + c0 + 2] * inv_d, stage[r0 * 20 + c0 + 3] * inv_d);
                v1 = make_float4(stage[r0 * 20 + c0 + 4] * inv_d, stage[r0 * 20 + c0 + 5] * inv_d,
                                 stage[r0 * 20 + c0 + 6] * inv_d, stage[r0 * 20 + c0 + 7] * inv_d);
            }
            *reinterpret_cast<float4*>(ob + (size_t)gs * D_ + ge)     = v0;
            *reinterpret_cast<float4*>(ob + (size_t)gs * D_ + ge + 4) = v1;
            __syncwarp();
        }
    }
}

// ---------------------------------------------------------------------------
extern "C" void kernel_launch(void* const* d_in, const int* in_sizes, int n_in,
                              void* d_out, int out_size) {
    const float* Q = reinterpret_cast<const float*>(d_in[0]);
    const float* K = reinterpret_cast<const float*>(d_in[1]);
    const float* V = reinterpret_cast<const float*>(d_in[2]);
    const void*  M = d_in[3];
    float* out = reinterpret_cast<float*>(d_out);

    cudaFuncSetAttribute(gemm1_kernel, cudaFuncAttributeMaxDynamicSharedMemorySize, G1_SMEM);
    cudaFuncSetAttribute(gemm2_kernel, cudaFuncAttributeMaxDynamicSharedMemorySize, G2_SMEM);

    zero_detect_kernel<<<2, 256>>>(reinterpret_cast<const unsigned int*>(M));
    {
        dim3 g(S_ / 32, B_, 2);
        prep_kernel<<<g, 256>>>(Q, K, V, M);
    }
    {
        dim3 g(4, NSPLIT, B_);
        gemm1_kernel<<<g, 256, G1_SMEM>>>();
    }
    s1conv_kernel<<<(B_ * D_ * D_) / (4 * 256), 256>>>();
    {
        dim3 g(2, S_ / 128, B_);
        gemm2_kernel<<<g, 256, G2_SMEM>>>(out);
    }
}

// round 8
// speedup vs baseline: 1.0009x; 1.0009x over previous
#include <cuda_runtime.h>
#include <cuda_bf16.h>
#include <mma.h>
#include <cstdint>

using namespace nvcuda;

#define NEGC -1000000000.0f
#define B_ 8
#define S_ 4096
#define D_ 256
#define KC 64
#define NSPLIT 8

// ---------------------------------------------------------------------------
// Scratch (__device__ globals; no allocation allowed)
// ---------------------------------------------------------------------------
__device__ __nv_bfloat16 g_Kc[B_ * S_ * D_];              // [b][s][d]  K * invb
__device__ __nv_bfloat16 g_Vc[B_ * S_ * D_];              // [b][s][e]  V
__device__ __nv_bfloat16 g_Qc[B_ * S_ * D_];              // [b][s][d]  Q/sumsq (masked=0)
__device__ float         g_s1part[NSPLIT * B_ * D_ * D_]; // per-split partials
__device__ __nv_bfloat16 g_s1c[B_ * D_ * D_];             // [b][d][e]  bf16 (reduced)
__device__ float         g_t[B_ * D_];                    // exact colsum (masked rows)
__device__ unsigned char g_msk[B_ * S_];
__device__ int           g_cnt[4 * B_];                   // per-tile completion counters
__device__ int           g_mask_mode;                     // 0=bool,1=int32,2=float32

// ---------------------------------------------------------------------------
// Helpers
// ---------------------------------------------------------------------------
__device__ __forceinline__ void cp16(void* smem_dst, const void* gsrc) {
    uint32_t a = (uint32_t)__cvta_generic_to_shared(smem_dst);
    asm volatile("cp.async.cg.shared.global [%0], [%1], 16;" :: "r"(a), "l"(gsrc));
}
__device__ __forceinline__ void cp_commit() { asm volatile("cp.async.commit_group;"); }
#define CP_WAIT(N) asm volatile("cp.async.wait_group %0;" :: "n"(N))

__device__ __forceinline__ uint4 pack8(float4 a, float4 b, float m) {
    __nv_bfloat162 h0 = __floats2bfloat162_rn(a.x * m, a.y * m);
    __nv_bfloat162 h1 = __floats2bfloat162_rn(a.z * m, a.w * m);
    __nv_bfloat162 h2 = __floats2bfloat162_rn(b.x * m, b.y * m);
    __nv_bfloat162 h3 = __floats2bfloat162_rn(b.z * m, b.w * m);
    uint4 o;
    o.x = *reinterpret_cast<uint32_t*>(&h0);
    o.y = *reinterpret_cast<uint32_t*>(&h1);
    o.z = *reinterpret_cast<uint32_t*>(&h2);
    o.w = *reinterpret_cast<uint32_t*>(&h3);
    return o;
}

// ---------------------------------------------------------------------------
// Block 0: zero g_t + counters.  Block 1: mask dtype detect.
// ---------------------------------------------------------------------------
__global__ void zero_detect_kernel(const unsigned int* __restrict__ m) {
    if (blockIdx.x == 0) {
        reinterpret_cast<float4*>(g_t)[threadIdx.x] = make_float4(0.f, 0.f, 0.f, 0.f);
        reinterpret_cast<float4*>(g_t)[threadIdx.x + 256] = make_float4(0.f, 0.f, 0.f, 0.f);
        if (threadIdx.x < 4 * B_) g_cnt[threadIdx.x] = 0;
    } else {
        __shared__ int s_big, s_odd;
        if (threadIdx.x == 0) { s_big = 0; s_odd = 0; }
        __syncthreads();
        int big = 0, odd = 0;
        for (int i = threadIdx.x; i < (B_ * S_) / 4; i += blockDim.x) {
            unsigned int w = m[i];
            unsigned int b0 = w & 0xFFu, b1 = (w >> 8) & 0xFFu,
                         b2 = (w >> 16) & 0xFFu, b3 = w >> 24;
            if (b0 > 1u || b1 > 1u || b2 > 1u || b3 > 1u) big = 1;
            if (w != 0u && w != 1u) odd = 1;
        }
        if (big) s_big = 1;
        if (odd) s_odd = 1;
        __syncthreads();
        if (threadIdx.x == 0) g_mask_mode = s_big ? 2 : (s_odd ? 0 : 1);
    }
}

// ---------------------------------------------------------------------------
// Fused prep.  z==0: KV pass (invb, Kc, Vc, exact t accumulation).
//              z==1: Q pass (sumsq, Qc, mask byte).
// grid (S/32, B, 2), 256 threads.
// ---------------------------------------------------------------------------
__global__ __launch_bounds__(256) void prep_kernel(const float* __restrict__ Q,
                                                   const float* __restrict__ K,
                                                   const float* __restrict__ V,
                                                   const void* __restrict__ m) {
    __shared__ float Vsm[32][264];
    __shared__ float csm[32];
    const int b = blockIdx.y, s0 = blockIdx.x * 32;
    const int tid = threadIdx.x, wid = tid >> 5, lane = tid & 31;
    const size_t base = ((size_t)b * S_ + s0) * D_;

    if (blockIdx.z == 0) {
#pragma unroll
        for (int i = 0; i < 4; i++) {
            int r = wid * 4 + i;
            const float4* kr = reinterpret_cast<const float4*>(K + base + (size_t)r * D_) + lane * 2;
            float4 k0 = kr[0], k1 = kr[1];
            float sk = k0.x * k0.x + k0.y * k0.y + k0.z * k0.z + k0.w * k0.w
                     + k1.x * k1.x + k1.y * k1.y + k1.z * k1.z + k1.w * k1.w;
            float rk = k0.x + k0.y + k0.z + k0.w + k1.x + k1.y + k1.z + k1.w;
#pragma unroll
            for (int o = 16; o; o >>= 1) {
                sk += __shfl_xor_sync(0xFFFFFFFFu, sk, o);
                rk += __shfl_xor_sync(0xFFFFFFFFu, rk, o);
            }
            float ib = 1.0f / sk;
            reinterpret_cast<uint4*>(g_Kc)[(base + (size_t)r * D_) / 8 + lane] = pack8(k0, k1, ib);

            const float4* vr = reinterpret_cast<const float4*>(V + base + (size_t)r * D_) + lane * 2;
            float4 v0 = vr[0], v1 = vr[1];
            *reinterpret_cast<float4*>(&Vsm[r][lane * 8])     = v0;
            *reinterpret_cast<float4*>(&Vsm[r][lane * 8 + 4]) = v1;
            reinterpret_cast<uint4*>(g_Vc)[(base + (size_t)r * D_) / 8 + lane] = pack8(v0, v1, 1.0f);
            if (lane == 0) csm[r] = rk * ib;
        }
        __syncthreads();
        float acc = 0.f;
        int e = tid;
#pragma unroll 8
        for (int s = 0; s < 32; s++) acc += csm[s] * Vsm[s][e];
        atomicAdd(&g_t[b * D_ + e], acc);
    } else {
        const int mode = g_mask_mode;
#pragma unroll
        for (int i = 0; i < 4; i++) {
            int r = wid * 4 + i;
            int g = b * S_ + s0 + r;
            const float4* qr = reinterpret_cast<const float4*>(Q + base + (size_t)r * D_) + lane * 2;
            float4 q0 = qr[0], q1 = qr[1];
            float sq = q0.x * q0.x + q0.y * q0.y + q0.z * q0.z + q0.w * q0.w
                     + q1.x * q1.x + q1.y * q1.y + q1.z * q1.z + q1.w * q1.w;
#pragma unroll
            for (int o = 16; o; o >>= 1) sq += __shfl_xor_sync(0xFFFFFFFFu, sq, o);
            bool mk;
            if (mode == 2)      mk = (reinterpret_cast<const float*>(m)[g] != 0.0f);
            else if (mode == 1) mk = (reinterpret_cast<const int*>(m)[g] != 0);
            else                mk = (reinterpret_cast<const unsigned char*>(m)[g] != 0);
            float mul = mk ? 0.0f : 1.0f / sq;
            reinterpret_cast<uint4*>(g_Qc)[(base + (size_t)r * D_) / 8 + lane] = pack8(q0, q1, mul);
            if (lane == 0) g_msk[g] = mk ? 1 : 0;
        }
    }
}

// ---------------------------------------------------------------------------
// GEMM1: s1part[split][b,d,e] = sum_{s in split} Kc[b,s,d] * Vc[b,s,e]
// 2-stage cp.async, 128x128 CTA, 8 warps (4x2, warp 32x64), 2 CTAs/SM.
// LAST CTA per (tile,b) reduces NSPLIT partials -> bf16 g_s1c (fuses s1conv).
// grid (4 tiles, NSPLIT, B).
// ---------------------------------------------------------------------------
#define AB1 8704               // 64*136 bf16 per operand per stage
#define G1_STAGE (2 * AB1)
#define G1_SMEM  (2 * G1_STAGE * (int)sizeof(__nv_bfloat16))   // 69632 B

__global__ __launch_bounds__(256, 2) void gemm1_kernel() {
    extern __shared__ __nv_bfloat16 dsm[];

    const int tid = threadIdx.x, wid = tid >> 5, lane = tid & 31;
    const int b = blockIdx.z;
    const int dt = (blockIdx.x >> 1) * 128, et = (blockIdx.x & 1) * 128;
    const int split = blockIdx.y;
    const int s0 = split * (S_ / NSPLIT);
    const int m0 = (wid >> 1) * 32, n0 = (wid & 1) * 64;
    const __nv_bfloat16* Kb = g_Kc + (size_t)b * S_ * D_;
    const __nv_bfloat16* Vb = g_Vc + (size_t)b * S_ * D_;

    wmma::fragment<wmma::accumulator, 16, 16, 16, float> acc[2][4];
#pragma unroll
    for (int i = 0; i < 2; i++)
#pragma unroll
        for (int j = 0; j < 4; j++) wmma::fill_fragment(acc[i][j], 0.0f);

    auto load = [&](int ch, int st) {
        const int ss = s0 + ch * KC;
        __nv_bfloat16* Ab = dsm + st * G1_STAGE;
        __nv_bfloat16* Bb = Ab + AB1;
#pragma unroll
        for (int it = 0; it < 4; it++) {
            int ci = tid + it * 256;
            int row = ci >> 4, c16 = ci & 15;
            cp16(Ab + row * 136 + c16 * 8, Kb + (size_t)(ss + row) * D_ + dt + c16 * 8);
            cp16(Bb + row * 136 + c16 * 8, Vb + (size_t)(ss + row) * D_ + et + c16 * 8);
        }
    };

    const int NCH = (S_ / NSPLIT) / KC;   // 8
    load(0, 0); cp_commit();
    for (int ch = 0; ch < NCH; ch++) {
        if (ch + 1 < NCH) { load(ch + 1, (ch + 1) & 1); cp_commit(); CP_WAIT(1); }
        else CP_WAIT(0);
        __syncthreads();
        __nv_bfloat16* Ab = dsm + (ch & 1) * G1_STAGE;
        __nv_bfloat16* Bb = Ab + AB1;
#pragma unroll
        for (int kk = 0; kk < KC / 16; kk++) {
            wmma::fragment<wmma::matrix_a, 16, 16, 16, __nv_bfloat16, wmma::col_major> fa[2];
            wmma::fragment<wmma::matrix_b, 16, 16, 16, __nv_bfloat16, wmma::row_major> fb[4];
#pragma unroll
            for (int i = 0; i < 2; i++)
                wmma::load_matrix_sync(fa[i], Ab + kk * 16 * 136 + m0 + 16 * i, 136);
#pragma unroll
            for (int j = 0; j < 4; j++)
                wmma::load_matrix_sync(fb[j], Bb + kk * 16 * 136 + n0 + 16 * j, 136);
#pragma unroll
            for (int i = 0; i < 2; i++)
#pragma unroll
                for (int j = 0; j < 4; j++)
                    wmma::mma_sync(acc[i][j], fa[i], fb[j], acc[i][j]);
        }
        __syncthreads();
    }

    // Epilogue: store partial (stage buffer aliased over dead pipeline smem).
    float* stage = reinterpret_cast<float*>(dsm) + wid * 16 * 20;
    float* s1p = g_s1part + ((size_t)split * B_ + b) * D_ * D_;
    int r0 = lane >> 1, c0 = (lane & 1) * 8;
#pragma unroll
    for (int i = 0; i < 2; i++)
#pragma unroll
        for (int j = 0; j < 4; j++) {
            wmma::store_matrix_sync(stage, acc[i][j], 20, wmma::mem_row_major);
            __syncwarp();
            int gd = dt + m0 + 16 * i + r0;
            int ge = et + n0 + 16 * j + c0;
            float4 v0 = *reinterpret_cast<float4*>(&stage[r0 * 20 + c0]);
            float4 v1 = *reinterpret_cast<float4*>(&stage[r0 * 20 + c0 + 4]);
            *reinterpret_cast<float4*>(&s1p[(size_t)gd * D_ + ge])     = v0;
            *reinterpret_cast<float4*>(&s1p[(size_t)gd * D_ + ge + 4]) = v1;
            __syncwarp();
        }

    // Last CTA of this (tile,b) reduces all NSPLIT partials -> bf16.
    __syncthreads();
    __shared__ int s_last;
    if (tid == 0) {
        __threadfence();
        int old = atomicAdd(&g_cnt[blockIdx.x * B_ + b], 1);
        s_last = (old == NSPLIT - 1);
    }
    __syncthreads();
    if (!s_last) return;
    __threadfence();

    const size_t tilebase = (size_t)b * D_ * D_;
    // 128 rows x 32 float4-cols = 4096 float4s; 16 per thread.
    for (int idx = tid; idx < 128 * 32; idx += 256) {
        int row = idx >> 5, c4 = idx & 31;
        size_t off = (size_t)(dt + row) * D_ + et + c4 * 4;
        float4 a = *reinterpret_cast<const float4*>(&g_s1part[(size_t)0 * B_ * D_ * D_ + tilebase + off]);
#pragma unroll
        for (int sp = 1; sp < NSPLIT; sp++) {
            float4 p = *reinterpret_cast<const float4*>(
                &g_s1part[(size_t)sp * B_ * D_ * D_ + tilebase + off]);
            a.x += p.x; a.y += p.y; a.z += p.z; a.w += p.w;
        }
        __nv_bfloat162 h0 = __floats2bfloat162_rn(a.x, a.y);
        __nv_bfloat162 h1 = __floats2bfloat162_rn(a.z, a.w);
        uint2 o;
        o.x = *reinterpret_cast<uint32_t*>(&h0);
        o.y = *reinterpret_cast<uint32_t*>(&h1);
        *reinterpret_cast<uint2*>(&g_s1c[tilebase + off]) = o;
    }
}

// ---------------------------------------------------------------------------
// GEMM2: out[b,s,e] = (1/256)*sum_d Qc[b,s,d]*s1c[b,d,e];
// masked rows -> NEG/256 * t[b,e] (exact fp32). 2-stage pipeline, 2 CTAs/SM.
// grid (2 et, 32 st, B).
// ---------------------------------------------------------------------------
#define A2BUF 9216             // 128*72
#define B2BUF 8704             // 64*136
#define G2_STAGE (A2BUF + B2BUF)
#define G2_SMEM  (2 * G2_STAGE * (int)sizeof(__nv_bfloat16))   // 71680 B

__global__ __launch_bounds__(256, 2) void gemm2_kernel(float* __restrict__ out) {
    extern __shared__ __nv_bfloat16 dsm[];

    const int tid = threadIdx.x, wid = tid >> 5, lane = tid & 31;
    const int b = blockIdx.z;
    const int et = blockIdx.x * 128, st = blockIdx.y * 128;
    const int m0 = (wid >> 1) * 32, n0 = (wid & 1) * 64;
    const __nv_bfloat16* Qb = g_Qc + ((size_t)b * S_ + st) * D_;
    const __nv_bfloat16* Sb = g_s1c + (size_t)b * D_ * D_;

    wmma::fragment<wmma::accumulator, 16, 16, 16, float> acc[2][4];
#pragma unroll
    for (int i = 0; i < 2; i++)
#pragma unroll
        for (int j = 0; j < 4; j++) wmma::fill_fragment(acc[i][j], 0.0f);

    auto load = [&](int ch, int st_) {
        __nv_bfloat16* Ab = dsm + st_ * G2_STAGE;
        __nv_bfloat16* Bb = Ab + A2BUF;
#pragma unroll
        for (int it = 0; it < 4; it++) {
            int ci = tid + it * 256;
            int arow = ci >> 3, ac8 = ci & 7;
            cp16(Ab + arow * 72 + ac8 * 8, Qb + (size_t)arow * D_ + ch * KC + ac8 * 8);
            int brow = ci >> 4, bc16 = ci & 15;
            cp16(Bb + brow * 136 + bc16 * 8, Sb + (size_t)(ch * KC + brow) * D_ + et + bc16 * 8);
        }
    };

    const int NCH = D_ / KC;   // 4
    load(0, 0); cp_commit();
    for (int ch = 0; ch < NCH; ch++) {
        if (ch + 1 < NCH) { load(ch + 1, (ch + 1) & 1); cp_commit(); CP_WAIT(1); }
        else CP_WAIT(0);
        __syncthreads();
        __nv_bfloat16* Ab = dsm + (ch & 1) * G2_STAGE;
        __nv_bfloat16* Bb = Ab + A2BUF;
#pragma unroll
        for (int kk = 0; kk < KC / 16; kk++) {
            wmma::fragment<wmma::matrix_a, 16, 16, 16, __nv_bfloat16, wmma::row_major> fa[2];
            wmma::fragment<wmma::matrix_b, 16, 16, 16, __nv_bfloat16, wmma::row_major> fb[4];
#pragma unroll
            for (int i = 0; i < 2; i++)
                wmma::load_matrix_sync(fa[i], Ab + (size_t)(m0 + 16 * i) * 72 + kk * 16, 72);
#pragma unroll
            for (int j = 0; j < 4; j++)
                wmma::load_matrix_sync(fb[j], Bb + kk * 16 * 136 + n0 + 16 * j, 136);
#pragma unroll
            for (int i = 0; i < 2; i++)
#pragma unroll
                for (int j = 0; j < 4; j++)
                    wmma::mma_sync(acc[i][j], fa[i], fb[j], acc[i][j]);
        }
        __syncthreads();
    }

    const float inv_d = 1.0f / 256.0f;
    const float mc = NEGC * inv_d;
    float* stage = reinterpret_cast<float*>(dsm) + wid * 16 * 20;
    float* ob = out + (size_t)b * S_ * D_;
    const float* tb = g_t + b * D_;
    int r0 = lane >> 1, c0 = (lane & 1) * 8;
#pragma unroll
    for (int i = 0; i < 2; i++) {
        int gs = st + m0 + 16 * i + r0;
        bool masked = (g_msk[b * S_ + gs] != 0);
#pragma unroll
        for (int j = 0; j < 4; j++) {
            wmma::store_matrix_sync(stage, acc[i][j], 20, wmma::mem_row_major);
            __syncwarp();
            int ge = et + n0 + 16 * j + c0;
            float4 v0, v1;
            if (masked) {
                v0 = make_float4(mc * tb[ge + 0], mc * tb[ge + 1], mc * tb[ge + 2], mc * tb[ge + 3]);
                v1 = make_float4(mc * tb[ge + 4], mc * tb[ge + 5], mc * tb[ge + 6], mc * tb[ge + 7]);
            } else {
                v0 = make_float4(stage[r0 * 20 + c0 + 0] * inv_d, stage[r0 * 20 + c0 + 1] * inv_d,
                                 stage[r0 * 20 + c0 + 2] * inv_d, stage[r0 * 20 + c0 + 3] * inv_d);
                v1 = make_float4(stage[r0 * 20 + c0 + 4] * inv_d, stage[r0 * 20 + c0 + 5] * inv_d,
                                 stage[r0 * 20 + c0 + 6] * inv_d, stage[r0 * 20 + c0 + 7] * inv_d);
            }
            *reinterpret_cast<float4*>(ob + (size_t)gs * D_ + ge)     = v0;
            *reinterpret_cast<float4*>(ob + (size_t)gs * D_ + ge + 4) = v1;
            __syncwarp();
        }
    }
}

// ---------------------------------------------------------------------------
extern "C" void kernel_launch(void* const* d_in, const int* in_sizes, int n_in,
                              void* d_out, int out_size) {
    const float* Q = reinterpret_cast<const float*>(d_in[0]);
    const float* K = reinterpret_cast<const float*>(d_in[1]);
    const float* V = reinterpret_cast<const float*>(d_in[2]);
    const void*  M = d_in[3];
    float* out = reinterpret_cast<float*>(d_out);

    cudaFuncSetAttribute(gemm1_kernel, cudaFuncAttributeMaxDynamicSharedMemorySize, G1_SMEM);
    cudaFuncSetAttribute(gemm2_kernel, cudaFuncAttributeMaxDynamicSharedMemorySize, G2_SMEM);

    zero_detect_kernel<<<2, 256>>>(reinterpret_cast<const unsigned int*>(M));
    {
        dim3 g(S_ / 32, B_, 2);
        prep_kernel<<<g, 256>>>(Q, K, V, M);
    }
    {
        dim3 g(4, NSPLIT, B_);
        gemm1_kernel<<<g, 256, G1_SMEM>>>();
    }
    {
        dim3 g(2, S_ / 128, B_);
        gemm2_kernel<<<g, 256, G2_SMEM>>>(out);
    }
}

// round 9
// speedup vs baseline: 1.3352x; 1.3340x over previous
#include <cuda_runtime.h>
#include <cuda_bf16.h>
#include <cstdint>

#define NEGC -1000000000.0f
#define B_ 8
#define S_ 4096
#define D_ 256
#define KC 128
#define NSPLIT 4

// ---------------------------------------------------------------------------
// Scratch (__device__ globals; no allocation allowed)
// ---------------------------------------------------------------------------
__device__ __nv_bfloat16 g_Kc[B_ * S_ * D_];              // [b][s][d]  K * invb
__device__ __nv_bfloat16 g_Vc[B_ * S_ * D_];              // [b][s][e]  V
__device__ __nv_bfloat16 g_Qc[B_ * S_ * D_];              // [b][s][d]  Q/sumsq (masked=0)
__device__ float         g_s1part[NSPLIT * B_ * D_ * D_]; // per-split partials
__device__ __nv_bfloat16 g_s1c[B_ * D_ * D_];             // [b][d][e]  bf16 (reduced)
__device__ float         g_t[B_ * D_];                    // exact colsum (masked rows)
__device__ unsigned char g_msk[B_ * S_];
__device__ int           g_mask_mode;                     // 0=bool,1=int32,2=float32

// ---------------------------------------------------------------------------
// Helpers
// ---------------------------------------------------------------------------
__device__ __forceinline__ void cp16(void* smem_dst, const void* gsrc) {
    uint32_t a = (uint32_t)__cvta_generic_to_shared(smem_dst);
    asm volatile("cp.async.cg.shared.global [%0], [%1], 16;" :: "r"(a), "l"(gsrc));
}
__device__ __forceinline__ void cp_commit() { asm volatile("cp.async.commit_group;"); }
#define CP_WAIT(N) asm volatile("cp.async.wait_group %0;" :: "n"(N))

__device__ __forceinline__ void ldsmx4(uint32_t* r, uint32_t addr) {
    asm volatile("ldmatrix.sync.aligned.m8n8.x4.shared.b16 {%0,%1,%2,%3}, [%4];"
                 : "=r"(r[0]), "=r"(r[1]), "=r"(r[2]), "=r"(r[3]) : "r"(addr));
}
__device__ __forceinline__ void ldsmx4t(uint32_t* r, uint32_t addr) {
    asm volatile("ldmatrix.sync.aligned.m8n8.x4.trans.shared.b16 {%0,%1,%2,%3}, [%4];"
                 : "=r"(r[0]), "=r"(r[1]), "=r"(r[2]), "=r"(r[3]) : "r"(addr));
}
__device__ __forceinline__ void mma16816(float* d, const uint32_t* a, const uint32_t* b) {
    asm volatile(
        "mma.sync.aligned.m16n8k16.row.col.f32.bf16.bf16.f32 "
        "{%0,%1,%2,%3},{%4,%5,%6,%7},{%8,%9},{%0,%1,%2,%3};"
        : "+f"(d[0]), "+f"(d[1]), "+f"(d[2]), "+f"(d[3])
        : "r"(a[0]), "r"(a[1]), "r"(a[2]), "r"(a[3]), "r"(b[0]), "r"(b[1]));
}

__device__ __forceinline__ uint4 pack8(float4 a, float4 b, float m) {
    __nv_bfloat162 h0 = __floats2bfloat162_rn(a.x * m, a.y * m);
    __nv_bfloat162 h1 = __floats2bfloat162_rn(a.z * m, a.w * m);
    __nv_bfloat162 h2 = __floats2bfloat162_rn(b.x * m, b.y * m);
    __nv_bfloat162 h3 = __floats2bfloat162_rn(b.z * m, b.w * m);
    uint4 o;
    o.x = *reinterpret_cast<uint32_t*>(&h0);
    o.y = *reinterpret_cast<uint32_t*>(&h1);
    o.z = *reinterpret_cast<uint32_t*>(&h2);
    o.w = *reinterpret_cast<uint32_t*>(&h3);
    return o;
}

// ---------------------------------------------------------------------------
// Block 0: zero g_t.  Block 1: mask dtype detect.
// ---------------------------------------------------------------------------
__global__ void zero_detect_kernel(const unsigned int* __restrict__ m) {
    if (blockIdx.x == 0) {
        reinterpret_cast<float4*>(g_t)[threadIdx.x] = make_float4(0.f, 0.f, 0.f, 0.f);
        reinterpret_cast<float4*>(g_t)[threadIdx.x + 256] = make_float4(0.f, 0.f, 0.f, 0.f);
    } else {
        __shared__ int s_big, s_odd;
        if (threadIdx.x == 0) { s_big = 0; s_odd = 0; }
        __syncthreads();
        int big = 0, odd = 0;
        for (int i = threadIdx.x; i < (B_ * S_) / 4; i += blockDim.x) {
            unsigned int w = m[i];
            unsigned int b0 = w & 0xFFu, b1 = (w >> 8) & 0xFFu,
                         b2 = (w >> 16) & 0xFFu, b3 = w >> 24;
            if (b0 > 1u || b1 > 1u || b2 > 1u || b3 > 1u) big = 1;
            if (w != 0u && w != 1u) odd = 1;
        }
        if (big) s_big = 1;
        if (odd) s_odd = 1;
        __syncthreads();
        if (threadIdx.x == 0) g_mask_mode = s_big ? 2 : (s_odd ? 0 : 1);
    }
}

// ---------------------------------------------------------------------------
// Fused prep.  z==0: KV pass (invb, Kc, Vc, exact t accumulation).
//              z==1: Q pass (sumsq, Qc, mask byte).
// grid (S/32, B, 2), 256 threads.
// ---------------------------------------------------------------------------
__global__ __launch_bounds__(256) void prep_kernel(const float* __restrict__ Q,
                                                   const float* __restrict__ K,
                                                   const float* __restrict__ V,
                                                   const void* __restrict__ m) {
    __shared__ float Vsm[32][264];
    __shared__ float csm[32];
    const int b = blockIdx.y, s0 = blockIdx.x * 32;
    const int tid = threadIdx.x, wid = tid >> 5, lane = tid & 31;
    const size_t base = ((size_t)b * S_ + s0) * D_;

    if (blockIdx.z == 0) {
#pragma unroll
        for (int i = 0; i < 4; i++) {
            int r = wid * 4 + i;
            const float4* kr = reinterpret_cast<const float4*>(K + base + (size_t)r * D_) + lane * 2;
            float4 k0 = kr[0], k1 = kr[1];
            float sk = k0.x * k0.x + k0.y * k0.y + k0.z * k0.z + k0.w * k0.w
                     + k1.x * k1.x + k1.y * k1.y + k1.z * k1.z + k1.w * k1.w;
            float rk = k0.x + k0.y + k0.z + k0.w + k1.x + k1.y + k1.z + k1.w;
#pragma unroll
            for (int o = 16; o; o >>= 1) {
                sk += __shfl_xor_sync(0xFFFFFFFFu, sk, o);
                rk += __shfl_xor_sync(0xFFFFFFFFu, rk, o);
            }
            float ib = 1.0f / sk;
            reinterpret_cast<uint4*>(g_Kc)[(base + (size_t)r * D_) / 8 + lane] = pack8(k0, k1, ib);

            const float4* vr = reinterpret_cast<const float4*>(V + base + (size_t)r * D_) + lane * 2;
            float4 v0 = vr[0], v1 = vr[1];
            *reinterpret_cast<float4*>(&Vsm[r][lane * 8])     = v0;
            *reinterpret_cast<float4*>(&Vsm[r][lane * 8 + 4]) = v1;
            reinterpret_cast<uint4*>(g_Vc)[(base + (size_t)r * D_) / 8 + lane] = pack8(v0, v1, 1.0f);
            if (lane == 0) csm[r] = rk * ib;
        }
        __syncthreads();
        float acc = 0.f;
        int e = tid;
#pragma unroll 8
        for (int s = 0; s < 32; s++) acc += csm[s] * Vsm[s][e];
        atomicAdd(&g_t[b * D_ + e], acc);
    } else {
        const int mode = g_mask_mode;
#pragma unroll
        for (int i = 0; i < 4; i++) {
            int r = wid * 4 + i;
            int g = b * S_ + s0 + r;
            const float4* qr = reinterpret_cast<const float4*>(Q + base + (size_t)r * D_) + lane * 2;
            float4 q0 = qr[0], q1 = qr[1];
            float sq = q0.x * q0.x + q0.y * q0.y + q0.z * q0.z + q0.w * q0.w
                     + q1.x * q1.x + q1.y * q1.y + q1.z * q1.z + q1.w * q1.w;
#pragma unroll
            for (int o = 16; o; o >>= 1) sq += __shfl_xor_sync(0xFFFFFFFFu, sq, o);
            bool mk;
            if (mode == 2)      mk = (reinterpret_cast<const float*>(m)[g] != 0.0f);
            else if (mode == 1) mk = (reinterpret_cast<const int*>(m)[g] != 0);
            else                mk = (reinterpret_cast<const unsigned char*>(m)[g] != 0);
            float mul = mk ? 0.0f : 1.0f / sq;
            reinterpret_cast<uint4*>(g_Qc)[(base + (size_t)r * D_) / 8 + lane] = pack8(q0, q1, mul);
            if (lane == 0) g_msk[g] = mk ? 1 : 0;
        }
    }
}

// ---------------------------------------------------------------------------
// Hand-rolled mma.sync GEMMs.
// Smem tile layout: [KC rows][128 + 8 pad cols] bf16, row stride SR=136.
// ---------------------------------------------------------------------------
#define SR 136
#define ABUF (KC * SR)             // elems per operand per stage (17408)
#define STG  (2 * ABUF)
#define GS_SMEM (2 * STG * (int)sizeof(__nv_bfloat16))   // 139264 B

// GEMM1: s1part[split][b,d,e] = sum_s Kc[b,s,d] * Vc[b,s,e]
// A operand (m=d,k=s) from [s][d] storage -> ldmatrix trans-pattern addressing.
// grid (4 tiles, NSPLIT, B), 256 threads, 8 warps (4m x 2n), warp 32x64.
__global__ __launch_bounds__(256) void gemm1_kernel() {
    extern __shared__ __nv_bfloat16 dsm[];

    const int tid = threadIdx.x, wid = tid >> 5, lane = tid & 31;
    const int b = blockIdx.z;
    const int dt = (blockIdx.x >> 1) * 128, et = (blockIdx.x & 1) * 128;
    const int s0 = blockIdx.y * (S_ / NSPLIT);
    const int m0 = (wid >> 1) * 32, n0 = (wid & 1) * 64;
    const __nv_bfloat16* Kb = g_Kc + (size_t)b * S_ * D_;
    const __nv_bfloat16* Vb = g_Vc + (size_t)b * S_ * D_;

    float acc[2][8][4];
#pragma unroll
    for (int i = 0; i < 2; i++)
#pragma unroll
        for (int j = 0; j < 8; j++)
#pragma unroll
            for (int q = 0; q < 4; q++) acc[i][j][q] = 0.f;

    // ldmatrix lane addressing
    const int r8 = lane & 7, sel = lane >> 3;
    const int atr = (sel >> 1) * 8 + r8, atc = (sel & 1) * 8;   // A trans pattern
    const int btr = (sel & 1) * 8 + r8, btc = (sel >> 1) * 8;   // B trans pattern

    auto load = [&](int ch, int st) {
        const int ss = s0 + ch * KC;
        __nv_bfloat16* Ab = dsm + st * STG;
        __nv_bfloat16* Bb = Ab + ABUF;
#pragma unroll
        for (int it = 0; it < 8; it++) {
            int ci = tid + it * 256;
            int row = ci >> 4, c16 = ci & 15;
            cp16(Ab + row * SR + c16 * 8, Kb + (size_t)(ss + row) * D_ + dt + c16 * 8);
            cp16(Bb + row * SR + c16 * 8, Vb + (size_t)(ss + row) * D_ + et + c16 * 8);
        }
    };

    const int NCH = (S_ / NSPLIT) / KC;   // 8
    load(0, 0); cp_commit();
    for (int ch = 0; ch < NCH; ch++) {
        if (ch + 1 < NCH) { load(ch + 1, (ch + 1) & 1); cp_commit(); CP_WAIT(1); }
        else CP_WAIT(0);
        __syncthreads();
        uint32_t Aaddr = (uint32_t)__cvta_generic_to_shared(dsm + (ch & 1) * STG);
        uint32_t Baddr = Aaddr + ABUF * 2;
#pragma unroll
        for (int kk = 0; kk < KC / 16; kk++) {
            uint32_t af[2][4], bf[4][4];
#pragma unroll
            for (int mt = 0; mt < 2; mt++)
                ldsmx4(af[mt], Aaddr + ((kk * 16 + atr) * SR + m0 + mt * 16 + atc) * 2);
#pragma unroll
            for (int nt = 0; nt < 4; nt++)
                ldsmx4t(bf[nt], Baddr + ((kk * 16 + btr) * SR + n0 + nt * 16 + btc) * 2);
#pragma unroll
            for (int mt = 0; mt < 2; mt++)
#pragma unroll
                for (int nt = 0; nt < 4; nt++) {
                    mma16816(acc[mt][nt * 2],     af[mt], &bf[nt][0]);
                    mma16816(acc[mt][nt * 2 + 1], af[mt], &bf[nt][2]);
                }
        }
        __syncthreads();
    }

    float* s1p = g_s1part + ((size_t)blockIdx.y * B_ + b) * D_ * D_;
    const int tr = lane >> 2, tc = (lane & 3) * 2;
#pragma unroll
    for (int mt = 0; mt < 2; mt++) {
        int gd0 = dt + m0 + mt * 16 + tr;
#pragma unroll
        for (int nt = 0; nt < 8; nt++) {
            int ge = et + n0 + nt * 8 + tc;
            *reinterpret_cast<float2*>(&s1p[(size_t)gd0 * D_ + ge]) =
                make_float2(acc[mt][nt][0], acc[mt][nt][1]);
            *reinterpret_cast<float2*>(&s1p[(size_t)(gd0 + 8) * D_ + ge]) =
                make_float2(acc[mt][nt][2], acc[mt][nt][3]);
        }
    }
}

// Reduce NSPLIT partials + convert to bf16.
__global__ void s1conv_kernel() {
    int i = blockIdx.x * 256 + threadIdx.x;   // B*D*D/4
    const int stride = (B_ * D_ * D_) / 4;
    float4 a = reinterpret_cast<const float4*>(g_s1part)[i];
#pragma unroll
    for (int sp = 1; sp < NSPLIT; sp++) {
        float4 p = reinterpret_cast<const float4*>(g_s1part)[sp * stride + i];
        a.x += p.x; a.y += p.y; a.z += p.z; a.w += p.w;
    }
    __nv_bfloat162 h0 = __floats2bfloat162_rn(a.x, a.y);
    __nv_bfloat162 h1 = __floats2bfloat162_rn(a.z, a.w);
    uint2 o;
    o.x = *reinterpret_cast<uint32_t*>(&h0);
    o.y = *reinterpret_cast<uint32_t*>(&h1);
    reinterpret_cast<uint2*>(g_s1c)[i] = o;
}

// GEMM2: out[b,s,e] = (1/256)*sum_d Qc[b,s,d]*s1c[b,d,e]; masked rows exact.
// A (m=s,k=d) from [s][d] storage -> non-trans pattern. grid (2 et, 32 st, B).
__global__ __launch_bounds__(256) void gemm2_kernel(float* __restrict__ out) {
    extern __shared__ __nv_bfloat16 dsm[];
    __shared__ float ts[128];

    const int tid = threadIdx.x, wid = tid >> 5, lane = tid & 31;
    const int b = blockIdx.z;
    const int et = blockIdx.x * 128, st = blockIdx.y * 128;
    const int m0 = (wid >> 1) * 32, n0 = (wid & 1) * 64;
    const __nv_bfloat16* Qb = g_Qc + ((size_t)b * S_ + st) * D_;
    const __nv_bfloat16* Sb = g_s1c + (size_t)b * D_ * D_;

    if (tid < 128) ts[tid] = g_t[b * D_ + et + tid];

    float acc[2][8][4];
#pragma unroll
    for (int i = 0; i < 2; i++)
#pragma unroll
        for (int j = 0; j < 8; j++)
#pragma unroll
            for (int q = 0; q < 4; q++) acc[i][j][q] = 0.f;

    const int r8 = lane & 7, sel = lane >> 3;
    const int anr = lane & 15, anc = (lane >> 4) * 8;           // A non-trans pattern
    const int btr = (sel & 1) * 8 + r8, btc = (sel >> 1) * 8;   // B trans pattern

    auto load = [&](int ch, int st_) {
        __nv_bfloat16* Ab = dsm + st_ * STG;
        __nv_bfloat16* Bb = Ab + ABUF;
#pragma unroll
        for (int it = 0; it < 8; it++) {
            int ci = tid + it * 256;
            int row = ci >> 4, c16 = ci & 15;
            cp16(Ab + row * SR + c16 * 8, Qb + (size_t)row * D_ + ch * KC + c16 * 8);
            cp16(Bb + row * SR + c16 * 8, Sb + (size_t)(ch * KC + row) * D_ + et + c16 * 8);
        }
    };

    const int NCH = D_ / KC;   // 2
    load(0, 0); cp_commit();
    for (int ch = 0; ch < NCH; ch++) {
        if (ch + 1 < NCH) { load(ch + 1, (ch + 1) & 1); cp_commit(); CP_WAIT(1); }
        else CP_WAIT(0);
        __syncthreads();
        uint32_t Aaddr = (uint32_t)__cvta_generic_to_shared(dsm + (ch & 1) * STG);
        uint32_t Baddr = Aaddr + ABUF * 2;
#pragma unroll
        for (int kk = 0; kk < KC / 16; kk++) {
            uint32_t af[2][4], bf[4][4];
#pragma unroll
            for (int mt = 0; mt < 2; mt++)
                ldsmx4(af[mt], Aaddr + ((m0 + mt * 16 + anr) * SR + kk * 16 + anc) * 2);
#pragma unroll
            for (int nt = 0; nt < 4; nt++)
                ldsmx4t(bf[nt], Baddr + ((kk * 16 + btr) * SR + n0 + nt * 16 + btc) * 2);
#pragma unroll
            for (int mt = 0; mt < 2; mt++)
#pragma unroll
                for (int nt = 0; nt < 4; nt++) {
                    mma16816(acc[mt][nt * 2],     af[mt], &bf[nt][0]);
                    mma16816(acc[mt][nt * 2 + 1], af[mt], &bf[nt][2]);
                }
        }
        __syncthreads();
    }

    const float inv_d = 1.0f / 256.0f;
    const float mc = NEGC * inv_d;
    float* ob = out + (size_t)b * S_ * D_;
    const int tr = lane >> 2, tc = (lane & 3) * 2;
#pragma unroll
    for (int mt = 0; mt < 2; mt++) {
        int r0l = m0 + mt * 16 + tr;
        int gs0 = st + r0l, gs1 = gs0 + 8;
        bool mk0 = (g_msk[b * S_ + gs0] != 0);
        bool mk1 = (g_msk[b * S_ + gs1] != 0);
#pragma unroll
        for (int nt = 0; nt < 8; nt++) {
            int gel = n0 + nt * 8 + tc;
            int ge = et + gel;
            float2 v0, v1;
            if (mk0) v0 = make_float2(mc * ts[gel], mc * ts[gel + 1]);
            else     v0 = make_float2(acc[mt][nt][0] * inv_d, acc[mt][nt][1] * inv_d);
            if (mk1) v1 = make_float2(mc * ts[gel], mc * ts[gel + 1]);
            else     v1 = make_float2(acc[mt][nt][2] * inv_d, acc[mt][nt][3] * inv_d);
            *reinterpret_cast<float2*>(&ob[(size_t)gs0 * D_ + ge]) = v0;
            *reinterpret_cast<float2*>(&ob[(size_t)gs1 * D_ + ge]) = v1;
        }
    }
}

// ---------------------------------------------------------------------------
extern "C" void kernel_launch(void* const* d_in, const int* in_sizes, int n_in,
                              void* d_out, int out_size) {
    const float* Q = reinterpret_cast<const float*>(d_in[0]);
    const float* K = reinterpret_cast<const float*>(d_in[1]);
    const float* V = reinterpret_cast<const float*>(d_in[2]);
    const void*  M = d_in[3];
    float* out = reinterpret_cast<float*>(d_out);

    cudaFuncSetAttribute(gemm1_kernel, cudaFuncAttributeMaxDynamicSharedMemorySize, GS_SMEM);
    cudaFuncSetAttribute(gemm2_kernel, cudaFuncAttributeMaxDynamicSharedMemorySize, GS_SMEM);

    zero_detect_kernel<<<2, 256>>>(reinterpret_cast<const unsigned int*>(M));
    {
        dim3 g(S_ / 32, B_, 2);
        prep_kernel<<<g, 256>>>(Q, K, V, M);
    }
    {
        dim3 g(4, NSPLIT, B_);
        gemm1_kernel<<<g, 256, GS_SMEM>>>();
    }
    s1conv_kernel<<<(B_ * D_ * D_) / (4 * 256), 256>>>();
    {
        dim3 g(2, S_ / 128, B_);
        gemm2_kernel<<<g, 256, GS_SMEM>>>(out);
    }
}

// round 10
// speedup vs baseline: 1.3707x; 1.0266x over previous
#include <cuda_runtime.h>
#include <cuda_bf16.h>
#include <cstdint>

#define NEGC -1000000000.0f
#define B_ 8
#define S_ 4096
#define D_ 256
#define KC 128
#define NSPLIT 8

// ---------------------------------------------------------------------------
// Scratch (__device__ globals; no allocation allowed)
// ---------------------------------------------------------------------------
__device__ __nv_bfloat16 g_Kc[B_ * S_ * D_];              // [b][s][d]  K * invb
__device__ __nv_bfloat16 g_Vc[B_ * S_ * D_];              // [b][s][e]  V
__device__ __nv_bfloat16 g_Qc[B_ * S_ * D_];              // [b][s][d]  Q/sumsq (masked=0)
__device__ float         g_s1part[NSPLIT * B_ * D_ * D_]; // per-split partials
__device__ __nv_bfloat16 g_s1c[B_ * D_ * D_];             // [b][d][e]  bf16 (reduced)
__device__ float         g_t[B_ * D_];                    // exact colsum (masked rows)
__device__ unsigned char g_msk[B_ * S_];
__device__ int           g_mask_mode;                     // 0=bool,1=int32,2=float32

// ---------------------------------------------------------------------------
// Helpers
// ---------------------------------------------------------------------------
__device__ __forceinline__ void cp16(void* smem_dst, const void* gsrc) {
    uint32_t a = (uint32_t)__cvta_generic_to_shared(smem_dst);
    asm volatile("cp.async.cg.shared.global [%0], [%1], 16;" :: "r"(a), "l"(gsrc));
}
__device__ __forceinline__ void cp_commit() { asm volatile("cp.async.commit_group;"); }
#define CP_WAIT(N) asm volatile("cp.async.wait_group %0;" :: "n"(N))

__device__ __forceinline__ void ldsmx4(uint32_t* r, uint32_t addr) {
    asm volatile("ldmatrix.sync.aligned.m8n8.x4.shared.b16 {%0,%1,%2,%3}, [%4];"
                 : "=r"(r[0]), "=r"(r[1]), "=r"(r[2]), "=r"(r[3]) : "r"(addr));
}
__device__ __forceinline__ void ldsmx4t(uint32_t* r, uint32_t addr) {
    asm volatile("ldmatrix.sync.aligned.m8n8.x4.trans.shared.b16 {%0,%1,%2,%3}, [%4];"
                 : "=r"(r[0]), "=r"(r[1]), "=r"(r[2]), "=r"(r[3]) : "r"(addr));
}
__device__ __forceinline__ void mma16816(float* d, const uint32_t* a, const uint32_t* b) {
    asm volatile(
        "mma.sync.aligned.m16n8k16.row.col.f32.bf16.bf16.f32 "
        "{%0,%1,%2,%3},{%4,%5,%6,%7},{%8,%9},{%0,%1,%2,%3};"
        : "+f"(d[0]), "+f"(d[1]), "+f"(d[2]), "+f"(d[3])
        : "r"(a[0]), "r"(a[1]), "r"(a[2]), "r"(a[3]), "r"(b[0]), "r"(b[1]));
}

__device__ __forceinline__ uint4 pack8(float4 a, float4 b, float m) {
    __nv_bfloat162 h0 = __floats2bfloat162_rn(a.x * m, a.y * m);
    __nv_bfloat162 h1 = __floats2bfloat162_rn(a.z * m, a.w * m);
    __nv_bfloat162 h2 = __floats2bfloat162_rn(b.x * m, b.y * m);
    __nv_bfloat162 h3 = __floats2bfloat162_rn(b.z * m, b.w * m);
    uint4 o;
    o.x = *reinterpret_cast<uint32_t*>(&h0);
    o.y = *reinterpret_cast<uint32_t*>(&h1);
    o.z = *reinterpret_cast<uint32_t*>(&h2);
    o.w = *reinterpret_cast<uint32_t*>(&h3);
    return o;
}

// ---------------------------------------------------------------------------
// Block 0: zero g_t.  Block 1: mask dtype detect.
// ---------------------------------------------------------------------------
__global__ void zero_detect_kernel(const unsigned int* __restrict__ m) {
    if (blockIdx.x == 0) {
        reinterpret_cast<float4*>(g_t)[threadIdx.x] = make_float4(0.f, 0.f, 0.f, 0.f);
        reinterpret_cast<float4*>(g_t)[threadIdx.x + 256] = make_float4(0.f, 0.f, 0.f, 0.f);
    } else {
        __shared__ int s_big, s_odd;
        if (threadIdx.x == 0) { s_big = 0; s_odd = 0; }
        __syncthreads();
        int big = 0, odd = 0;
        for (int i = threadIdx.x; i < (B_ * S_) / 4; i += blockDim.x) {
            unsigned int w = m[i];
            unsigned int b0 = w & 0xFFu, b1 = (w >> 8) & 0xFFu,
                         b2 = (w >> 16) & 0xFFu, b3 = w >> 24;
            if (b0 > 1u || b1 > 1u || b2 > 1u || b3 > 1u) big = 1;
            if (w != 0u && w != 1u) odd = 1;
        }
        if (big) s_big = 1;
        if (odd) s_odd = 1;
        __syncthreads();
        if (threadIdx.x == 0) g_mask_mode = s_big ? 2 : (s_odd ? 0 : 1);
    }
}

// ---------------------------------------------------------------------------
// Fused prep.  z==0: KV pass (invb, Kc, Vc, exact t accumulation).
//              z==1: Q pass (sumsq, Qc, mask byte).
// grid (S/32, B, 2), 256 threads.
// ---------------------------------------------------------------------------
__global__ __launch_bounds__(256) void prep_kernel(const float* __restrict__ Q,
                                                   const float* __restrict__ K,
                                                   const float* __restrict__ V,
                                                   const void* __restrict__ m) {
    __shared__ float Vsm[32][264];
    __shared__ float csm[32];
    const int b = blockIdx.y, s0 = blockIdx.x * 32;
    const int tid = threadIdx.x, wid = tid >> 5, lane = tid & 31;
    const size_t base = ((size_t)b * S_ + s0) * D_;

    if (blockIdx.z == 0) {
#pragma unroll
        for (int i = 0; i < 4; i++) {
            int r = wid * 4 + i;
            const float4* kr = reinterpret_cast<const float4*>(K + base + (size_t)r * D_) + lane * 2;
            float4 k0 = kr[0], k1 = kr[1];
            float sk = k0.x * k0.x + k0.y * k0.y + k0.z * k0.z + k0.w * k0.w
                     + k1.x * k1.x + k1.y * k1.y + k1.z * k1.z + k1.w * k1.w;
            float rk = k0.x + k0.y + k0.z + k0.w + k1.x + k1.y + k1.z + k1.w;
#pragma unroll
            for (int o = 16; o; o >>= 1) {
                sk += __shfl_xor_sync(0xFFFFFFFFu, sk, o);
                rk += __shfl_xor_sync(0xFFFFFFFFu, rk, o);
            }
            float ib = 1.0f / sk;
            reinterpret_cast<uint4*>(g_Kc)[(base + (size_t)r * D_) / 8 + lane] = pack8(k0, k1, ib);

            const float4* vr = reinterpret_cast<const float4*>(V + base + (size_t)r * D_) + lane * 2;
            float4 v0 = vr[0], v1 = vr[1];
            *reinterpret_cast<float4*>(&Vsm[r][lane * 8])     = v0;
            *reinterpret_cast<float4*>(&Vsm[r][lane * 8 + 4]) = v1;
            reinterpret_cast<uint4*>(g_Vc)[(base + (size_t)r * D_) / 8 + lane] = pack8(v0, v1, 1.0f);
            if (lane == 0) csm[r] = rk * ib;
        }
        __syncthreads();
        float acc = 0.f;
        int e = tid;
#pragma unroll 8
        for (int s = 0; s < 32; s++) acc += csm[s] * Vsm[s][e];
        atomicAdd(&g_t[b * D_ + e], acc);
    } else {
        const int mode = g_mask_mode;
#pragma unroll
        for (int i = 0; i < 4; i++) {
            int r = wid * 4 + i;
            int g = b * S_ + s0 + r;
            const float4* qr = reinterpret_cast<const float4*>(Q + base + (size_t)r * D_) + lane * 2;
            float4 q0 = qr[0], q1 = qr[1];
            float sq = q0.x * q0.x + q0.y * q0.y + q0.z * q0.z + q0.w * q0.w
                     + q1.x * q1.x + q1.y * q1.y + q1.z * q1.z + q1.w * q1.w;
#pragma unroll
            for (int o = 16; o; o >>= 1) sq += __shfl_xor_sync(0xFFFFFFFFu, sq, o);
            bool mk;
            if (mode == 2)      mk = (reinterpret_cast<const float*>(m)[g] != 0.0f);
            else if (mode == 1) mk = (reinterpret_cast<const int*>(m)[g] != 0);
            else                mk = (reinterpret_cast<const unsigned char*>(m)[g] != 0);
            float mul = mk ? 0.0f : 1.0f / sq;
            reinterpret_cast<uint4*>(g_Qc)[(base + (size_t)r * D_) / 8 + lane] = pack8(q0, q1, mul);
            if (lane == 0) g_msk[g] = mk ? 1 : 0;
        }
    }
}

// ---------------------------------------------------------------------------
// GEMM1: CTA tile 256(d) x 128(e).  8 warps (4m x 2n), warp tile 64x64.
// A = Kc[s][d] (trans ldmatrix), all 256 d-cols; B = Vc[s][e] half.
// grid (2 et, NSPLIT, B) = 128 CTAs (one wave). 2-stage cp.async, KC=128.
// ---------------------------------------------------------------------------
#define SRA1 264                       // A smem row stride (256+8)
#define SRB  136                       // B smem row stride (128+8)
#define A1BUF (KC * SRA1)              // 33792 elems
#define B1BUF (KC * SRB)               // 17408 elems
#define STG1  (A1BUF + B1BUF)          // 51200 elems
#define G1_SMEM (2 * STG1 * (int)sizeof(__nv_bfloat16))   // 204800 B

__global__ __launch_bounds__(256) void gemm1_kernel() {
    extern __shared__ __nv_bfloat16 dsm[];

    const int tid = threadIdx.x, wid = tid >> 5, lane = tid & 31;
    const int b = blockIdx.z;
    const int et = blockIdx.x * 128;
    const int s0 = blockIdx.y * (S_ / NSPLIT);
    const int m0 = (wid >> 1) * 64, n0 = (wid & 1) * 64;
    const __nv_bfloat16* Kb = g_Kc + (size_t)b * S_ * D_;
    const __nv_bfloat16* Vb = g_Vc + (size_t)b * S_ * D_;

    float acc[4][8][4];
#pragma unroll
    for (int i = 0; i < 4; i++)
#pragma unroll
        for (int j = 0; j < 8; j++)
#pragma unroll
            for (int q = 0; q < 4; q++) acc[i][j][q] = 0.f;

    const int r8 = lane & 7, sel = lane >> 3;
    const int atr = (sel >> 1) * 8 + r8, atc = (sel & 1) * 8;   // A trans pattern
    const int btr = (sel & 1) * 8 + r8, btc = (sel >> 1) * 8;   // B trans pattern

    auto load = [&](int ch, int st) {
        const int ss = s0 + ch * KC;
        __nv_bfloat16* Ab = dsm + st * STG1;
        __nv_bfloat16* Bb = Ab + A1BUF;
        // A: 128 rows x 32 col16s = 4096 cp16
#pragma unroll
        for (int it = 0; it < 16; it++) {
            int ci = tid + it * 256;
            int row = ci >> 5, c16 = ci & 31;
            cp16(Ab + row * SRA1 + c16 * 8, Kb + (size_t)(ss + row) * D_ + c16 * 8);
        }
        // B: 128 rows x 16 col16s = 2048 cp16
#pragma unroll
        for (int it = 0; it < 8; it++) {
            int ci = tid + it * 256;
            int row = ci >> 4, c16 = ci & 15;
            cp16(Bb + row * SRB + c16 * 8, Vb + (size_t)(ss + row) * D_ + et + c16 * 8);
        }
    };

    const int NCH = (S_ / NSPLIT) / KC;   // 4
    load(0, 0); cp_commit();
    for (int ch = 0; ch < NCH; ch++) {
        if (ch + 1 < NCH) { load(ch + 1, (ch + 1) & 1); cp_commit(); CP_WAIT(1); }
        else CP_WAIT(0);
        __syncthreads();
        uint32_t Aaddr = (uint32_t)__cvta_generic_to_shared(dsm + (ch & 1) * STG1);
        uint32_t Baddr = Aaddr + A1BUF * 2;
#pragma unroll
        for (int kk = 0; kk < KC / 16; kk++) {
            uint32_t af[4][4], bf[4][4];
#pragma unroll
            for (int mt = 0; mt < 4; mt++)
                ldsmx4(af[mt], Aaddr + ((kk * 16 + atr) * SRA1 + m0 + mt * 16 + atc) * 2);
#pragma unroll
            for (int nt = 0; nt < 4; nt++)
                ldsmx4t(bf[nt], Baddr + ((kk * 16 + btr) * SRB + n0 + nt * 16 + btc) * 2);
#pragma unroll
            for (int mt = 0; mt < 4; mt++)
#pragma unroll
                for (int nt = 0; nt < 4; nt++) {
                    mma16816(acc[mt][nt * 2],     af[mt], &bf[nt][0]);
                    mma16816(acc[mt][nt * 2 + 1], af[mt], &bf[nt][2]);
                }
        }
        __syncthreads();
    }

    float* s1p = g_s1part + ((size_t)blockIdx.y * B_ + b) * D_ * D_;
    const int tr = lane >> 2, tc = (lane & 3) * 2;
#pragma unroll
    for (int mt = 0; mt < 4; mt++) {
        int gd0 = m0 + mt * 16 + tr;
#pragma unroll
        for (int nt = 0; nt < 8; nt++) {
            int ge = et + n0 + nt * 8 + tc;
            *reinterpret_cast<float2*>(&s1p[(size_t)gd0 * D_ + ge]) =
                make_float2(acc[mt][nt][0], acc[mt][nt][1]);
            *reinterpret_cast<float2*>(&s1p[(size_t)(gd0 + 8) * D_ + ge]) =
                make_float2(acc[mt][nt][2], acc[mt][nt][3]);
        }
    }
}

// Reduce NSPLIT partials + convert to bf16.  2 outputs/thread for ILP.
__global__ __launch_bounds__(256) void s1conv_kernel() {
    const int stride = (B_ * D_ * D_) / 4;
    int i0 = blockIdx.x * 512 + threadIdx.x;
    int i1 = i0 + 256;
    float4 a0 = reinterpret_cast<const float4*>(g_s1part)[i0];
    float4 a1 = reinterpret_cast<const float4*>(g_s1part)[i1];
#pragma unroll
    for (int sp = 1; sp < NSPLIT; sp++) {
        float4 p0 = reinterpret_cast<const float4*>(g_s1part)[sp * stride + i0];
        float4 p1 = reinterpret_cast<const float4*>(g_s1part)[sp * stride + i1];
        a0.x += p0.x; a0.y += p0.y; a0.z += p0.z; a0.w += p0.w;
        a1.x += p1.x; a1.y += p1.y; a1.z += p1.z; a1.w += p1.w;
    }
    __nv_bfloat162 h0 = __floats2bfloat162_rn(a0.x, a0.y);
    __nv_bfloat162 h1 = __floats2bfloat162_rn(a0.z, a0.w);
    uint2 o0 = {*reinterpret_cast<uint32_t*>(&h0), *reinterpret_cast<uint32_t*>(&h1)};
    reinterpret_cast<uint2*>(g_s1c)[i0] = o0;
    __nv_bfloat162 h2 = __floats2bfloat162_rn(a1.x, a1.y);
    __nv_bfloat162 h3 = __floats2bfloat162_rn(a1.z, a1.w);
    uint2 o1 = {*reinterpret_cast<uint32_t*>(&h2), *reinterpret_cast<uint32_t*>(&h3)};
    reinterpret_cast<uint2*>(g_s1c)[i1] = o1;
}

// ---------------------------------------------------------------------------
// GEMM2: CTA tile 256(s) x 128(e). 8 warps (4m x 2n), warp 64x64.
// A = Qc[s][d] (non-trans), B = s1c[d][e] (trans).  Masked rows exact.
// grid (2 et, 16 st, B) = 256 CTAs.  2-stage, KC=128, NCH=2.
// ---------------------------------------------------------------------------
#define SRA2 136
#define A2BUF (256 * SRA2)             // 34816 elems
#define B2BUF (KC * SRB)               // 17408 elems
#define STG2  (A2BUF + B2BUF)          // 52224 elems
#define G2_SMEM (2 * STG2 * (int)sizeof(__nv_bfloat16))   // 208896 B

__global__ __launch_bounds__(256) void gemm2_kernel(float* __restrict__ out) {
    extern __shared__ __nv_bfloat16 dsm[];
    __shared__ float ts[128];

    const int tid = threadIdx.x, wid = tid >> 5, lane = tid & 31;
    const int b = blockIdx.z;
    const int et = blockIdx.x * 128, st = blockIdx.y * 256;
    const int m0 = (wid >> 1) * 64, n0 = (wid & 1) * 64;
    const __nv_bfloat16* Qb = g_Qc + ((size_t)b * S_ + st) * D_;
    const __nv_bfloat16* Sb = g_s1c + (size_t)b * D_ * D_;

    if (tid < 128) ts[tid] = g_t[b * D_ + et + tid];

    float acc[4][8][4];
#pragma unroll
    for (int i = 0; i < 4; i++)
#pragma unroll
        for (int j = 0; j < 8; j++)
#pragma unroll
            for (int q = 0; q < 4; q++) acc[i][j][q] = 0.f;

    const int r8 = lane & 7, sel = lane >> 3;
    const int anr = lane & 15, anc = (lane >> 4) * 8;           // A non-trans
    const int btr = (sel & 1) * 8 + r8, btc = (sel >> 1) * 8;   // B trans

    auto load = [&](int ch, int st_) {
        __nv_bfloat16* Ab = dsm + st_ * STG2;
        __nv_bfloat16* Bb = Ab + A2BUF;
        // A: 256 rows x 16 col16s = 4096 cp16
#pragma unroll
        for (int it = 0; it < 16; it++) {
            int ci = tid + it * 256;
            int row = ci >> 4, c16 = ci & 15;
            cp16(Ab + row * SRA2 + c16 * 8, Qb + (size_t)row * D_ + ch * KC + c16 * 8);
        }
        // B: 128 rows x 16 col16s = 2048 cp16
#pragma unroll
        for (int it = 0; it < 8; it++) {
            int ci = tid + it * 256;
            int row = ci >> 4, c16 = ci & 15;
            cp16(Bb + row * SRB + c16 * 8, Sb + (size_t)(ch * KC + row) * D_ + et + c16 * 8);
        }
    };

    const int NCH = D_ / KC;   // 2
    load(0, 0); cp_commit();
    for (int ch = 0; ch < NCH; ch++) {
        if (ch + 1 < NCH) { load(ch + 1, (ch + 1) & 1); cp_commit(); CP_WAIT(1); }
        else CP_WAIT(0);
        __syncthreads();
        uint32_t Aaddr = (uint32_t)__cvta_generic_to_shared(dsm + (ch & 1) * STG2);
        uint32_t Baddr = Aaddr + A2BUF * 2;
#pragma unroll
        for (int kk = 0; kk < KC / 16; kk++) {
            uint32_t af[4][4], bf[4][4];
#pragma unroll
            for (int mt = 0; mt < 4; mt++)
                ldsmx4(af[mt], Aaddr + ((m0 + mt * 16 + anr) * SRA2 + kk * 16 + anc) * 2);
#pragma unroll
            for (int nt = 0; nt < 4; nt++)
                ldsmx4t(bf[nt], Baddr + ((kk * 16 + btr) * SRB + n0 + nt * 16 + btc) * 2);
#pragma unroll
            for (int mt = 0; mt < 4; mt++)
#pragma unroll
                for (int nt = 0; nt < 4; nt++) {
                    mma16816(acc[mt][nt * 2],     af[mt], &bf[nt][0]);
                    mma16816(acc[mt][nt * 2 + 1], af[mt], &bf[nt][2]);
                }
        }
        __syncthreads();
    }

    const float inv_d = 1.0f / 256.0f;
    const float mc = NEGC * inv_d;
    float* ob = out + (size_t)b * S_ * D_;
    const int tr = lane >> 2, tc = (lane & 3) * 2;
#pragma unroll
    for (int mt = 0; mt < 4; mt++) {
        int r0l = m0 + mt * 16 + tr;
        int gs0 = st + r0l, gs1 = gs0 + 8;
        bool mk0 = (g_msk[b * S_ + gs0] != 0);
        bool mk1 = (g_msk[b * S_ + gs1] != 0);
#pragma unroll
        for (int nt = 0; nt < 8; nt++) {
            int gel = n0 + nt * 8 + tc;
            int ge = et + gel;
            float2 v0, v1;
            if (mk0) v0 = make_float2(mc * ts[gel], mc * ts[gel + 1]);
            else     v0 = make_float2(acc[mt][nt][0] * inv_d, acc[mt][nt][1] * inv_d);
            if (mk1) v1 = make_float2(mc * ts[gel], mc * ts[gel + 1]);
            else     v1 = make_float2(acc[mt][nt][2] * inv_d, acc[mt][nt][3] * inv_d);
            *reinterpret_cast<float2*>(&ob[(size_t)gs0 * D_ + ge]) = v0;
            *reinterpret_cast<float2*>(&ob[(size_t)gs1 * D_ + ge]) = v1;
        }
    }
}

// ---------------------------------------------------------------------------
extern "C" void kernel_launch(void* const* d_in, const int* in_sizes, int n_in,
                              void* d_out, int out_size) {
    const float* Q = reinterpret_cast<const float*>(d_in[0]);
    const float* K = reinterpret_cast<const float*>(d_in[1]);
    const float* V = reinterpret_cast<const float*>(d_in[2]);
    const void*  M = d_in[3];
    float* out = reinterpret_cast<float*>(d_out);

    cudaFuncSetAttribute(gemm1_kernel, cudaFuncAttributeMaxDynamicSharedMemorySize, G1_SMEM);
    cudaFuncSetAttribute(gemm2_kernel, cudaFuncAttributeMaxDynamicSharedMemorySize, G2_SMEM);

    zero_detect_kernel<<<2, 256>>>(reinterpret_cast<const unsigned int*>(M));
    {
        dim3 g(S_ / 32, B_, 2);
        prep_kernel<<<g, 256>>>(Q, K, V, M);
    }
    {
        dim3 g(2, NSPLIT, B_);
        gemm1_kernel<<<g, 256, G1_SMEM>>>();
    }
    s1conv_kernel<<<(B_ * D_ * D_) / (4 * 512), 256>>>();
    {
        dim3 g(2, S_ / 256, B_);
        gemm2_kernel<<<g, 256, G2_SMEM>>>(out);
    }
}

// round 11
// speedup vs baseline: 1.3785x; 1.0058x over previous
#include <cuda_runtime.h>
#include <cuda_bf16.h>
#include <cstdint>

#define NEGC -1000000000.0f
#define B_ 8
#define S_ 4096
#define D_ 256
#define KC 128
#define NSPLIT 8

// ---------------------------------------------------------------------------
// Scratch (__device__ globals; no allocation allowed)
// ---------------------------------------------------------------------------
__device__ __nv_bfloat16 g_Kc[B_ * S_ * D_];              // [b][s][d]  K * invb
__device__ __nv_bfloat16 g_Vc[B_ * S_ * D_];              // [b][s][e]  V
__device__ __nv_bfloat16 g_Qc[B_ * S_ * D_];              // [b][s][d]  Q/sumsq (masked=0)
__device__ __nv_bfloat16 g_s1part[NSPLIT * B_ * D_ * D_]; // per-split partials (bf16)
__device__ __nv_bfloat16 g_s1c[B_ * D_ * D_];             // [b][d][e]  bf16 (reduced)
__device__ float         g_t[B_ * D_];                    // exact colsum (masked rows)
__device__ unsigned char g_msk[B_ * S_];
__device__ int           g_mask_mode;                     // 0=bool,1=int32,2=float32

// ---------------------------------------------------------------------------
// Helpers
// ---------------------------------------------------------------------------
__device__ __forceinline__ void cp16(void* smem_dst, const void* gsrc) {
    uint32_t a = (uint32_t)__cvta_generic_to_shared(smem_dst);
    asm volatile("cp.async.cg.shared.global [%0], [%1], 16;" :: "r"(a), "l"(gsrc));
}
__device__ __forceinline__ void cp_commit() { asm volatile("cp.async.commit_group;"); }
#define CP_WAIT(N) asm volatile("cp.async.wait_group %0;" :: "n"(N))

__device__ __forceinline__ void ldsmx4(uint32_t* r, uint32_t addr) {
    asm volatile("ldmatrix.sync.aligned.m8n8.x4.shared.b16 {%0,%1,%2,%3}, [%4];"
                 : "=r"(r[0]), "=r"(r[1]), "=r"(r[2]), "=r"(r[3]) : "r"(addr));
}
__device__ __forceinline__ void ldsmx4t(uint32_t* r, uint32_t addr) {
    asm volatile("ldmatrix.sync.aligned.m8n8.x4.trans.shared.b16 {%0,%1,%2,%3}, [%4];"
                 : "=r"(r[0]), "=r"(r[1]), "=r"(r[2]), "=r"(r[3]) : "r"(addr));
}
__device__ __forceinline__ void mma16816(float* d, const uint32_t* a, const uint32_t* b) {
    asm volatile(
        "mma.sync.aligned.m16n8k16.row.col.f32.bf16.bf16.f32 "
        "{%0,%1,%2,%3},{%4,%5,%6,%7},{%8,%9},{%0,%1,%2,%3};"
        : "+f"(d[0]), "+f"(d[1]), "+f"(d[2]), "+f"(d[3])
        : "r"(a[0]), "r"(a[1]), "r"(a[2]), "r"(a[3]), "r"(b[0]), "r"(b[1]));
}

__device__ __forceinline__ uint4 pack8(float4 a, float4 b, float m) {
    __nv_bfloat162 h0 = __floats2bfloat162_rn(a.x * m, a.y * m);
    __nv_bfloat162 h1 = __floats2bfloat162_rn(a.z * m, a.w * m);
    __nv_bfloat162 h2 = __floats2bfloat162_rn(b.x * m, b.y * m);
    __nv_bfloat162 h3 = __floats2bfloat162_rn(b.z * m, b.w * m);
    uint4 o;
    o.x = *reinterpret_cast<uint32_t*>(&h0);
    o.y = *reinterpret_cast<uint32_t*>(&h1);
    o.z = *reinterpret_cast<uint32_t*>(&h2);
    o.w = *reinterpret_cast<uint32_t*>(&h3);
    return o;
}

// ---------------------------------------------------------------------------
// Block 0: zero g_t.  Block 1: mask dtype detect.
// ---------------------------------------------------------------------------
__global__ void zero_detect_kernel(const unsigned int* __restrict__ m) {
    if (blockIdx.x == 0) {
        reinterpret_cast<float4*>(g_t)[threadIdx.x] = make_float4(0.f, 0.f, 0.f, 0.f);
        reinterpret_cast<float4*>(g_t)[threadIdx.x + 256] = make_float4(0.f, 0.f, 0.f, 0.f);
    } else {
        __shared__ int s_big, s_odd;
        if (threadIdx.x == 0) { s_big = 0; s_odd = 0; }
        __syncthreads();
        int big = 0, odd = 0;
        for (int i = threadIdx.x; i < (B_ * S_) / 4; i += blockDim.x) {
            unsigned int w = m[i];
            unsigned int b0 = w & 0xFFu, b1 = (w >> 8) & 0xFFu,
                         b2 = (w >> 16) & 0xFFu, b3 = w >> 24;
            if (b0 > 1u || b1 > 1u || b2 > 1u || b3 > 1u) big = 1;
            if (w != 0u && w != 1u) odd = 1;
        }
        if (big) s_big = 1;
        if (odd) s_odd = 1;
        __syncthreads();
        if (threadIdx.x == 0) g_mask_mode = s_big ? 2 : (s_odd ? 0 : 1);
    }
}

// ---------------------------------------------------------------------------
// Fused prep.  z==0: KV pass (invb, Kc, Vc, exact t accumulation).
//              z==1: Q pass (sumsq, Qc, mask byte).
// grid (S/32, B, 2), 256 threads.
// ---------------------------------------------------------------------------
__global__ __launch_bounds__(256) void prep_kernel(const float* __restrict__ Q,
                                                   const float* __restrict__ K,
                                                   const float* __restrict__ V,
                                                   const void* __restrict__ m) {
    __shared__ float Vsm[32][264];
    __shared__ float csm[32];
    const int b = blockIdx.y, s0 = blockIdx.x * 32;
    const int tid = threadIdx.x, wid = tid >> 5, lane = tid & 31;
    const size_t base = ((size_t)b * S_ + s0) * D_;

    if (blockIdx.z == 0) {
#pragma unroll
        for (int i = 0; i < 4; i++) {
            int r = wid * 4 + i;
            const float4* kr = reinterpret_cast<const float4*>(K + base + (size_t)r * D_) + lane * 2;
            float4 k0 = kr[0], k1 = kr[1];
            float sk = k0.x * k0.x + k0.y * k0.y + k0.z * k0.z + k0.w * k0.w
                     + k1.x * k1.x + k1.y * k1.y + k1.z * k1.z + k1.w * k1.w;
            float rk = k0.x + k0.y + k0.z + k0.w + k1.x + k1.y + k1.z + k1.w;
#pragma unroll
            for (int o = 16; o; o >>= 1) {
                sk += __shfl_xor_sync(0xFFFFFFFFu, sk, o);
                rk += __shfl_xor_sync(0xFFFFFFFFu, rk, o);
            }
            float ib = 1.0f / sk;
            reinterpret_cast<uint4*>(g_Kc)[(base + (size_t)r * D_) / 8 + lane] = pack8(k0, k1, ib);

            const float4* vr = reinterpret_cast<const float4*>(V + base + (size_t)r * D_) + lane * 2;
            float4 v0 = vr[0], v1 = vr[1];
            *reinterpret_cast<float4*>(&Vsm[r][lane * 8])     = v0;
            *reinterpret_cast<float4*>(&Vsm[r][lane * 8 + 4]) = v1;
            reinterpret_cast<uint4*>(g_Vc)[(base + (size_t)r * D_) / 8 + lane] = pack8(v0, v1, 1.0f);
            if (lane == 0) csm[r] = rk * ib;
        }
        __syncthreads();
        float acc = 0.f;
        int e = tid;
#pragma unroll 8
        for (int s = 0; s < 32; s++) acc += csm[s] * Vsm[s][e];
        atomicAdd(&g_t[b * D_ + e], acc);
    } else {
        const int mode = g_mask_mode;
#pragma unroll
        for (int i = 0; i < 4; i++) {
            int r = wid * 4 + i;
            int g = b * S_ + s0 + r;
            const float4* qr = reinterpret_cast<const float4*>(Q + base + (size_t)r * D_) + lane * 2;
            float4 q0 = qr[0], q1 = qr[1];
            float sq = q0.x * q0.x + q0.y * q0.y + q0.z * q0.z + q0.w * q0.w
                     + q1.x * q1.x + q1.y * q1.y + q1.z * q1.z + q1.w * q1.w;
#pragma unroll
            for (int o = 16; o; o >>= 1) sq += __shfl_xor_sync(0xFFFFFFFFu, sq, o);
            bool mk;
            if (mode == 2)      mk = (reinterpret_cast<const float*>(m)[g] != 0.0f);
            else if (mode == 1) mk = (reinterpret_cast<const int*>(m)[g] != 0);
            else                mk = (reinterpret_cast<const unsigned char*>(m)[g] != 0);
            float mul = mk ? 0.0f : 1.0f / sq;
            reinterpret_cast<uint4*>(g_Qc)[(base + (size_t)r * D_) / 8 + lane] = pack8(q0, q1, mul);
            if (lane == 0) g_msk[g] = mk ? 1 : 0;
        }
    }
}

// ---------------------------------------------------------------------------
// GEMM1: CTA tile 256(d) x 128(e).  8 warps (4m x 2n), warp tile 64x64.
// A = Kc[s][d] (trans ldmatrix), all 256 d-cols; B = Vc[s][e] half.
// Partials stored as bf16 (numerically safe: s1 feeds only unmasked rows).
// grid (2 et, NSPLIT, B) = 128 CTAs.  2-stage cp.async, KC=128.
// ---------------------------------------------------------------------------
#define SRA1 264                       // A smem row stride (256+8)
#define SRB  136                       // B smem row stride (128+8)
#define A1BUF (KC * SRA1)
#define B1BUF (KC * SRB)
#define STG1  (A1BUF + B1BUF)
#define G1_SMEM (2 * STG1 * (int)sizeof(__nv_bfloat16))   // 204800 B

__global__ __launch_bounds__(256) void gemm1_kernel() {
    extern __shared__ __nv_bfloat16 dsm[];

    const int tid = threadIdx.x, wid = tid >> 5, lane = tid & 31;
    const int b = blockIdx.z;
    const int et = blockIdx.x * 128;
    const int s0 = blockIdx.y * (S_ / NSPLIT);
    const int m0 = (wid >> 1) * 64, n0 = (wid & 1) * 64;
    const __nv_bfloat16* Kb = g_Kc + (size_t)b * S_ * D_;
    const __nv_bfloat16* Vb = g_Vc + (size_t)b * S_ * D_;

    float acc[4][8][4];
#pragma unroll
    for (int i = 0; i < 4; i++)
#pragma unroll
        for (int j = 0; j < 8; j++)
#pragma unroll
            for (int q = 0; q < 4; q++) acc[i][j][q] = 0.f;

    const int r8 = lane & 7, sel = lane >> 3;
    const int atr = (sel >> 1) * 8 + r8, atc = (sel & 1) * 8;   // A trans pattern
    const int btr = (sel & 1) * 8 + r8, btc = (sel >> 1) * 8;   // B trans pattern

    auto load = [&](int ch, int st) {
        const int ss = s0 + ch * KC;
        __nv_bfloat16* Ab = dsm + st * STG1;
        __nv_bfloat16* Bb = Ab + A1BUF;
#pragma unroll
        for (int it = 0; it < 16; it++) {
            int ci = tid + it * 256;
            int row = ci >> 5, c16 = ci & 31;
            cp16(Ab + row * SRA1 + c16 * 8, Kb + (size_t)(ss + row) * D_ + c16 * 8);
        }
#pragma unroll
        for (int it = 0; it < 8; it++) {
            int ci = tid + it * 256;
            int row = ci >> 4, c16 = ci & 15;
            cp16(Bb + row * SRB + c16 * 8, Vb + (size_t)(ss + row) * D_ + et + c16 * 8);
        }
    };

    const int NCH = (S_ / NSPLIT) / KC;   // 4
    load(0, 0); cp_commit();
    for (int ch = 0; ch < NCH; ch++) {
        if (ch + 1 < NCH) { load(ch + 1, (ch + 1) & 1); cp_commit(); CP_WAIT(1); }
        else CP_WAIT(0);
        __syncthreads();
        uint32_t Aaddr = (uint32_t)__cvta_generic_to_shared(dsm + (ch & 1) * STG1);
        uint32_t Baddr = Aaddr + A1BUF * 2;
#pragma unroll
        for (int kk = 0; kk < KC / 16; kk++) {
            uint32_t af[4][4], bf[4][4];
#pragma unroll
            for (int mt = 0; mt < 4; mt++)
                ldsmx4(af[mt], Aaddr + ((kk * 16 + atr) * SRA1 + m0 + mt * 16 + atc) * 2);
#pragma unroll
            for (int nt = 0; nt < 4; nt++)
                ldsmx4t(bf[nt], Baddr + ((kk * 16 + btr) * SRB + n0 + nt * 16 + btc) * 2);
#pragma unroll
            for (int mt = 0; mt < 4; mt++)
#pragma unroll
                for (int nt = 0; nt < 4; nt++) {
                    mma16816(acc[mt][nt * 2],     af[mt], &bf[nt][0]);
                    mma16816(acc[mt][nt * 2 + 1], af[mt], &bf[nt][2]);
                }
        }
        __syncthreads();
    }

    // Epilogue: convert to bf16, 32-bit stores into split partial.
    __nv_bfloat16* s1p = g_s1part + ((size_t)blockIdx.y * B_ + b) * D_ * D_;
    const int tr = lane >> 2, tc = (lane & 3) * 2;
#pragma unroll
    for (int mt = 0; mt < 4; mt++) {
        int gd0 = m0 + mt * 16 + tr;
#pragma unroll
        for (int nt = 0; nt < 8; nt++) {
            int ge = et + n0 + nt * 8 + tc;
            __nv_bfloat162 lo = __floats2bfloat162_rn(acc[mt][nt][0], acc[mt][nt][1]);
            __nv_bfloat162 hi = __floats2bfloat162_rn(acc[mt][nt][2], acc[mt][nt][3]);
            *reinterpret_cast<uint32_t*>(&s1p[(size_t)gd0 * D_ + ge]) =
                *reinterpret_cast<uint32_t*>(&lo);
            *reinterpret_cast<uint32_t*>(&s1p[(size_t)(gd0 + 8) * D_ + ge]) =
                *reinterpret_cast<uint32_t*>(&hi);
        }
    }
}

// Reduce NSPLIT bf16 partials (fp32 accumulate) -> bf16.  1 uint4 / thread.
__global__ __launch_bounds__(256) void s1conv_kernel() {
    const int i = blockIdx.x * 256 + threadIdx.x;   // uint4 index, B*D*D/8 total
    const int stride = (B_ * D_ * D_) / 8;
    float s[8] = {0.f, 0.f, 0.f, 0.f, 0.f, 0.f, 0.f, 0.f};
#pragma unroll
    for (int sp = 0; sp < NSPLIT; sp++) {
        uint4 p = reinterpret_cast<const uint4*>(g_s1part)[sp * stride + i];
        float2 f0 = __bfloat1622float2(*reinterpret_cast<__nv_bfloat162*>(&p.x));
        float2 f1 = __bfloat1622float2(*reinterpret_cast<__nv_bfloat162*>(&p.y));
        float2 f2 = __bfloat1622float2(*reinterpret_cast<__nv_bfloat162*>(&p.z));
        float2 f3 = __bfloat1622float2(*reinterpret_cast<__nv_bfloat162*>(&p.w));
        s[0] += f0.x; s[1] += f0.y; s[2] += f1.x; s[3] += f1.y;
        s[4] += f2.x; s[5] += f2.y; s[6] += f3.x; s[7] += f3.y;
    }
    __nv_bfloat162 h0 = __floats2bfloat162_rn(s[0], s[1]);
    __nv_bfloat162 h1 = __floats2bfloat162_rn(s[2], s[3]);
    __nv_bfloat162 h2 = __floats2bfloat162_rn(s[4], s[5]);
    __nv_bfloat162 h3 = __floats2bfloat162_rn(s[6], s[7]);
    uint4 o;
    o.x = *reinterpret_cast<uint32_t*>(&h0);
    o.y = *reinterpret_cast<uint32_t*>(&h1);
    o.z = *reinterpret_cast<uint32_t*>(&h2);
    o.w = *reinterpret_cast<uint32_t*>(&h3);
    reinterpret_cast<uint4*>(g_s1c)[i] = o;
}

// ---------------------------------------------------------------------------
// GEMM2: CTA tile 256(s) x 128(e). 8 warps (4m x 2n), warp 64x64.
// A = Qc[s][d] (non-trans), B = s1c[d][e] (trans).  Masked rows exact.
// grid (2 et, 16 st, B) = 256 CTAs.  2-stage, KC=128, NCH=2.
// ---------------------------------------------------------------------------
#define SRA2 136
#define A2BUF (256 * SRA2)
#define B2BUF (KC * SRB)
#define STG2  (A2BUF + B2BUF)
#define G2_SMEM (2 * STG2 * (int)sizeof(__nv_bfloat16))   // 208896 B

__global__ __launch_bounds__(256) void gemm2_kernel(float* __restrict__ out) {
    extern __shared__ __nv_bfloat16 dsm[];
    __shared__ float ts[128];

    const int tid = threadIdx.x, wid = tid >> 5, lane = tid & 31;
    const int b = blockIdx.z;
    const int et = blockIdx.x * 128, st = blockIdx.y * 256;
    const int m0 = (wid >> 1) * 64, n0 = (wid & 1) * 64;
    const __nv_bfloat16* Qb = g_Qc + ((size_t)b * S_ + st) * D_;
    const __nv_bfloat16* Sb = g_s1c + (size_t)b * D_ * D_;

    if (tid < 128) ts[tid] = g_t[b * D_ + et + tid];

    float acc[4][8][4];
#pragma unroll
    for (int i = 0; i < 4; i++)
#pragma unroll
        for (int j = 0; j < 8; j++)
#pragma unroll
            for (int q = 0; q < 4; q++) acc[i][j][q] = 0.f;

    const int r8 = lane & 7, sel = lane >> 3;
    const int anr = lane & 15, anc = (lane >> 4) * 8;           // A non-trans
    const int btr = (sel & 1) * 8 + r8, btc = (sel >> 1) * 8;   // B trans

    auto load = [&](int ch, int st_) {
        __nv_bfloat16* Ab = dsm + st_ * STG2;
        __nv_bfloat16* Bb = Ab + A2BUF;
#pragma unroll
        for (int it = 0; it < 16; it++) {
            int ci = tid + it * 256;
            int row = ci >> 4, c16 = ci & 15;
            cp16(Ab + row * SRA2 + c16 * 8, Qb + (size_t)row * D_ + ch * KC + c16 * 8);
        }
#pragma unroll
        for (int it = 0; it < 8; it++) {
            int ci = tid + it * 256;
            int row = ci >> 4, c16 = ci & 15;
            cp16(Bb + row * SRB + c16 * 8, Sb + (size_t)(ch * KC + row) * D_ + et + c16 * 8);
        }
    };

    const int NCH = D_ / KC;   // 2
    load(0, 0); cp_commit();
    for (int ch = 0; ch < NCH; ch++) {
        if (ch + 1 < NCH) { load(ch + 1, (ch + 1) & 1); cp_commit(); CP_WAIT(1); }
        else CP_WAIT(0);
        __syncthreads();
        uint32_t Aaddr = (uint32_t)__cvta_generic_to_shared(dsm + (ch & 1) * STG2);
        uint32_t Baddr = Aaddr + A2BUF * 2;
#pragma unroll
        for (int kk = 0; kk < KC / 16; kk++) {
            uint32_t af[4][4], bf[4][4];
#pragma unroll
            for (int mt = 0; mt < 4; mt++)
                ldsmx4(af[mt], Aaddr + ((m0 + mt * 16 + anr) * SRA2 + kk * 16 + anc) * 2);
#pragma unroll
            for (int nt = 0; nt < 4; nt++)
                ldsmx4t(bf[nt], Baddr + ((kk * 16 + btr) * SRB + n0 + nt * 16 + btc) * 2);
#pragma unroll
            for (int mt = 0; mt < 4; mt++)
#pragma unroll
                for (int nt = 0; nt < 4; nt++) {
                    mma16816(acc[mt][nt * 2],     af[mt], &bf[nt][0]);
                    mma16816(acc[mt][nt * 2 + 1], af[mt], &bf[nt][2]);
                }
        }
        __syncthreads();
    }

    const float inv_d = 1.0f / 256.0f;
    const float mc = NEGC * inv_d;
    float* ob = out + (size_t)b * S_ * D_;
    const int tr = lane >> 2, tc = (lane & 3) * 2;
#pragma unroll
    for (int mt = 0; mt < 4; mt++) {
        int r0l = m0 + mt * 16 + tr;
        int gs0 = st + r0l, gs1 = gs0 + 8;
        bool mk0 = (g_msk[b * S_ + gs0] != 0);
        bool mk1 = (g_msk[b * S_ + gs1] != 0);
#pragma unroll
        for (int nt = 0; nt < 8; nt++) {
            int gel = n0 + nt * 8 + tc;
            int ge = et + gel;
            float2 v0, v1;
            if (mk0) v0 = make_float2(mc * ts[gel], mc * ts[gel + 1]);
            else     v0 = make_float2(acc[mt][nt][0] * inv_d, acc[mt][nt][1] * inv_d);
            if (mk1) v1 = make_float2(mc * ts[gel], mc * ts[gel + 1]);
            else     v1 = make_float2(acc[mt][nt][2] * inv_d, acc[mt][nt][3] * inv_d);
            *reinterpret_cast<float2*>(&ob[(size_t)gs0 * D_ + ge]) = v0;
            *reinterpret_cast<float2*>(&ob[(size_t)gs1 * D_ + ge]) = v1;
        }
    }
}

// ---------------------------------------------------------------------------
extern "C" void kernel_launch(void* const* d_in, const int* in_sizes, int n_in,
                              void* d_out, int out_size) {
    const float* Q = reinterpret_cast<const float*>(d_in[0]);
    const float* K = reinterpret_cast<const float*>(d_in[1]);
    const float* V = reinterpret_cast<const float*>(d_in[2]);
    const void*  M = d_in[3];
    float* out = reinterpret_cast<float*>(d_out);

    cudaFuncSetAttribute(gemm1_kernel, cudaFuncAttributeMaxDynamicSharedMemorySize, G1_SMEM);
    cudaFuncSetAttribute(gemm2_kernel, cudaFuncAttributeMaxDynamicSharedMemorySize, G2_SMEM);

    zero_detect_kernel<<<2, 256>>>(reinterpret_cast<const unsigned int*>(M));
    {
        dim3 g(S_ / 32, B_, 2);
        prep_kernel<<<g, 256>>>(Q, K, V, M);
    }
    {
        dim3 g(2, NSPLIT, B_);
        gemm1_kernel<<<g, 256, G1_SMEM>>>();
    }
    s1conv_kernel<<<(B_ * D_ * D_) / (8 * 256), 256>>>();
    {
        dim3 g(2, S_ / 256, B_);
        gemm2_kernel<<<g, 256, G2_SMEM>>>(out);
    }
}